// round 2
// baseline (speedup 1.0000x reference)
#include <cuda_runtime.h>
#include <cstdint>

#define B_  8
#define T_  2048
#define C_  1024
#define H_  64
#define BT_  (B_ * T_)          // 16384
#define BTH_ (BT_ * H_)         // 1048576

// ---------------- device scratch (no allocations allowed) ----------------
__device__ float g_W3[192 * 1024];          // rows 0-63: Wq, 64-127: E^T Wk, 128-191: F^T Wv
__device__ float g_qkv[3 * BTH_];           // [Q | Kp | Vp], each [B,T,H] row-major

__device__ __forceinline__ float ex2f(float x) {
    float y;
    asm("ex2.approx.ftz.f32 %0, %1;" : "=f"(y) : "f"(x));
    return y;
}

// ---------------- kernel 1: fuse E/F into the K/V projection weights ----------------
// Wcomb[64+d][c]  = sum_h E[h][d] * Wk[h][c]   (k_proj = x @ (E^T Wk)^T)
// Wcomb[128+d][c] = sum_h F[h][d] * Wv[h][c]
__global__ void combine_w_kernel(const float* __restrict__ Wq, const float* __restrict__ Wk,
                                 const float* __restrict__ Wv, const float* __restrict__ E,
                                 const float* __restrict__ F) {
    int idx = blockIdx.x * 256 + threadIdx.x;     // 192*1024 total
    int n = idx >> 10, c = idx & 1023;
    float val;
    if (n < 64) {
        val = Wq[n * 1024 + c];
    } else if (n < 128) {
        int d = n - 64;
        float s = 0.f;
        #pragma unroll
        for (int h = 0; h < 64; ++h) s += E[h * 64 + d] * Wk[h * 1024 + c];
        val = s;
    } else {
        int d = n - 128;
        float s = 0.f;
        #pragma unroll
        for (int h = 0; h < 64; ++h) s += F[h * 64 + d] * Wv[h * 1024 + c];
        val = s;
    }
    g_W3[n * 1024 + c] = val;
}

// ---------------- kernel 2: projection GEMM ----------------
// Y[16384][192] = x[16384][1024] @ W3^T, written into g_qkv as 3 separate [BT][64] tensors.
// Tile: 128(M) x 64(N) x 16(K), 256 threads, 8x4 per-thread microtile.
__global__ __launch_bounds__(256) void proj_gemm_kernel(const float* __restrict__ x) {
    __shared__ float As[16][132];   // [k][m], padded to dodge store conflicts
    __shared__ float Bs[16][64];    // [k][n]

    const int m0 = blockIdx.x * 128;
    const int n0 = blockIdx.y * 64;         // 0 -> Q, 64 -> Kp, 128 -> Vp
    const int tid = threadIdx.x;
    const int tx = tid & 15, ty = tid >> 4;

    float acc[8][4];
    #pragma unroll
    for (int r = 0; r < 8; ++r)
        #pragma unroll
        for (int c = 0; c < 4; ++c) acc[r][c] = 0.f;

    const float* xA = x + (size_t)m0 * 1024;
    const float* wB = g_W3 + (size_t)n0 * 1024;

    for (int kt = 0; kt < 1024; kt += 16) {
        // A tile: 128x16 = 512 float4, 2 per thread
        #pragma unroll
        for (int u = 0; u < 2; ++u) {
            int fi = tid + u * 256;
            int row = fi >> 2, kk = (fi & 3) * 4;
            float4 v = *(const float4*)(xA + (size_t)row * 1024 + kt + kk);
            As[kk + 0][row] = v.x; As[kk + 1][row] = v.y;
            As[kk + 2][row] = v.z; As[kk + 3][row] = v.w;
        }
        // B tile: 64x16 = 256 float4, 1 per thread
        {
            int row = tid >> 2, kk = (tid & 3) * 4;
            float4 v = *(const float4*)(wB + (size_t)row * 1024 + kt + kk);
            Bs[kk + 0][row] = v.x; Bs[kk + 1][row] = v.y;
            Bs[kk + 2][row] = v.z; Bs[kk + 3][row] = v.w;
        }
        __syncthreads();
        #pragma unroll
        for (int k = 0; k < 16; ++k) {
            float a[8], b[4];
            #pragma unroll
            for (int r = 0; r < 8; ++r) a[r] = As[k][ty * 8 + r];
            #pragma unroll
            for (int c = 0; c < 4; ++c) b[c] = Bs[k][tx * 4 + c];
            #pragma unroll
            for (int r = 0; r < 8; ++r)
                #pragma unroll
                for (int c = 0; c < 4; ++c) acc[r][c] += a[r] * b[c];
        }
        __syncthreads();
    }

    float* outp = g_qkv + (size_t)blockIdx.y * BTH_;
    #pragma unroll
    for (int r = 0; r < 8; ++r) {
        int m = m0 + ty * 8 + r;
        float4 v = make_float4(acc[r][0], acc[r][1], acc[r][2], acc[r][3]);
        *(float4*)(outp + (size_t)m * 64 + tx * 4) = v;
    }
}

// ---------------- kernel 3: causal flash attention ----------------
// Block = 64 query rows (one 64-row tile of one batch), key tiles of 128.
// 256 blocks, 128 threads each, launched largest-qt-first for LPT packing.
// smem: Qt[64][64] (h-major) + Kt[64][128] (h-major) + Vs[128][64] + Ps[64][128]
#define ATTN_SMEM 114688

__global__ __launch_bounds__(128) void attn_kernel(float* __restrict__ out) {
    extern __shared__ float sm[];
    float* Qt = sm;                    // Qt[h*64 + i]
    float* Kt = Qt + 64 * 64;          // Kt[h*128 + j]
    float* Vs = Kt + 64 * 128;         // Vs[j*64 + h]
    float* Ps = Vs + 128 * 64;         // Ps[i*128 + j]

    const int b  = blockIdx.y;
    const int qt = 31 - blockIdx.x;    // descending work size
    const int tid = threadIdx.x;
    const int tx = tid & 15;           // 0..15 -> key cols / out cols
    const int ty = tid >> 4;           // 0..7  -> query rows
    const int i0 = ty * 8;
    const int rowg0 = qt * 64;

    const float* Qg = g_qkv + ((size_t)(b * T_) + rowg0) * H_;
    const float* Kg = g_qkv + BTH_ + (size_t)(b * T_) * H_;
    const float* Vg = g_qkv + 2 * BTH_ + (size_t)(b * T_) * H_;

    // load Q tile transposed, folding scale * log2(e)
    const float qscale = 0.0625f * 1.4426950408889634f;
    for (int u = tid; u < 64 * 16; u += 128) {
        int row = u >> 4, h4 = (u & 15) * 4;
        float4 v = *(const float4*)(Qg + (size_t)row * 64 + h4);
        Qt[(h4 + 0) * 64 + row] = v.x * qscale;
        Qt[(h4 + 1) * 64 + row] = v.y * qscale;
        Qt[(h4 + 2) * 64 + row] = v.z * qscale;
        Qt[(h4 + 3) * 64 + row] = v.w * qscale;
    }

    float m_i[8], l_i[8], o[8][4];
    #pragma unroll
    for (int r = 0; r < 8; ++r) {
        m_i[r] = -1e30f; l_i[r] = 0.f;
        #pragma unroll
        for (int c = 0; c < 4; ++c) o[r][c] = 0.f;
    }

    const int ntiles = ((qt * 64 + 63) >> 7) + 1;
    for (int kt = 0; kt < ntiles; ++kt) {
        __syncthreads();   // covers Qt on iter 0; protects Kt/Vs/Ps reuse afterwards
        const float* Kp = Kg + (size_t)kt * 128 * 64;
        const float* Vp = Vg + (size_t)kt * 128 * 64;
        for (int u = tid; u < 2048; u += 128) {
            int row = u >> 4, h4 = (u & 15) * 4;
            float4 kv = *(const float4*)(Kp + (size_t)row * 64 + h4);
            Kt[(h4 + 0) * 128 + row] = kv.x;
            Kt[(h4 + 1) * 128 + row] = kv.y;
            Kt[(h4 + 2) * 128 + row] = kv.z;
            Kt[(h4 + 3) * 128 + row] = kv.w;
            *(float4*)(Vs + (size_t)row * 64 + h4) = *(const float4*)(Vp + (size_t)row * 64 + h4);
        }
        __syncthreads();

        // S = Q @ K^T  (8x8 fragment per thread), already in log2 domain
        float s[8][8];
        #pragma unroll
        for (int r = 0; r < 8; ++r)
            #pragma unroll
            for (int c = 0; c < 8; ++c) s[r][c] = 0.f;

        #pragma unroll 8
        for (int h = 0; h < 64; ++h) {
            float4 a0 = *(const float4*)(Qt + h * 64 + i0);
            float4 a1 = *(const float4*)(Qt + h * 64 + i0 + 4);
            float4 b0 = *(const float4*)(Kt + h * 128 + tx * 8);
            float4 b1 = *(const float4*)(Kt + h * 128 + tx * 8 + 4);
            float a[8] = {a0.x, a0.y, a0.z, a0.w, a1.x, a1.y, a1.z, a1.w};
            float bb[8] = {b0.x, b0.y, b0.z, b0.w, b1.x, b1.y, b1.z, b1.w};
            #pragma unroll
            for (int r = 0; r < 8; ++r)
                #pragma unroll
                for (int c = 0; c < 8; ++c) s[r][c] += a[r] * bb[c];
        }

        // causal mask (only tiles that can cross the diagonal)
        if (kt * 128 + 127 > rowg0) {
            #pragma unroll
            for (int r = 0; r < 8; ++r) {
                int ig = rowg0 + i0 + r;
                #pragma unroll
                for (int c = 0; c < 8; ++c) {
                    int jg = kt * 128 + tx * 8 + c;
                    if (jg > ig) s[r][c] = -1e30f;
                }
            }
        }

        // online softmax (base-2)
        #pragma unroll
        for (int r = 0; r < 8; ++r) {
            float mx = s[r][0];
            #pragma unroll
            for (int c = 1; c < 8; ++c) mx = fmaxf(mx, s[r][c]);
            #pragma unroll
            for (int off = 1; off < 16; off <<= 1)
                mx = fmaxf(mx, __shfl_xor_sync(0xffffffffu, mx, off));
            float mnew = fmaxf(m_i[r], mx);
            float alpha = ex2f(m_i[r] - mnew);
            m_i[r] = mnew;
            l_i[r] *= alpha;
            #pragma unroll
            for (int c = 0; c < 4; ++c) o[r][c] *= alpha;
            float rs = 0.f;
            #pragma unroll
            for (int c = 0; c < 8; ++c) {
                float p = ex2f(s[r][c] - mnew);
                s[r][c] = p;
                rs += p;
            }
            #pragma unroll
            for (int off = 1; off < 16; off <<= 1)
                rs += __shfl_xor_sync(0xffffffffu, rs, off);
            l_i[r] += rs;
        }

        // spill P to smem for the PV GEMM
        #pragma unroll
        for (int r = 0; r < 8; ++r) {
            *(float4*)(Ps + (i0 + r) * 128 + tx * 8)     = make_float4(s[r][0], s[r][1], s[r][2], s[r][3]);
            *(float4*)(Ps + (i0 + r) * 128 + tx * 8 + 4) = make_float4(s[r][4], s[r][5], s[r][6], s[r][7]);
        }
        __syncthreads();

        // O += P @ V
        #pragma unroll 4
        for (int j = 0; j < 128; ++j) {
            float4 v = *(const float4*)(Vs + j * 64 + tx * 4);
            #pragma unroll
            for (int r = 0; r < 8; ++r) {
                float p = Ps[(i0 + r) * 128 + j];
                o[r][0] += p * v.x; o[r][1] += p * v.y;
                o[r][2] += p * v.z; o[r][3] += p * v.w;
            }
        }
    }

    // epilogue: normalize and store
    #pragma unroll
    for (int r = 0; r < 8; ++r) {
        float inv = 1.0f / l_i[r];
        size_t rowglob = (size_t)b * T_ + rowg0 + i0 + r;
        float4 v = make_float4(o[r][0] * inv, o[r][1] * inv, o[r][2] * inv, o[r][3] * inv);
        *(float4*)(out + rowglob * 64 + tx * 4) = v;
    }
}

// ---------------- launch ----------------
extern "C" void kernel_launch(void* const* d_in, const int* in_sizes, int n_in,
                              void* d_out, int out_size) {
    const float* x  = (const float*)d_in[0];
    const float* Wq = (const float*)d_in[1];
    const float* Wk = (const float*)d_in[2];
    const float* Wv = (const float*)d_in[3];
    const float* E  = (const float*)d_in[4];
    const float* F  = (const float*)d_in[5];
    float* out = (float*)d_out;

    combine_w_kernel<<<(192 * 1024) / 256, 256>>>(Wq, Wk, Wv, E, F);

    dim3 g2(BT_ / 128, 3);
    proj_gemm_kernel<<<g2, 256>>>(x);

    cudaFuncSetAttribute(attn_kernel, cudaFuncAttributeMaxDynamicSharedMemorySize, ATTN_SMEM);
    attn_kernel<<<dim3(32, B_), 128, ATTN_SMEM>>>(out);
}

// round 4
// speedup vs baseline: 1.1579x; 1.1579x over previous
#include <cuda_runtime.h>
#include <cuda_bf16.h>
#include <cstdint>

#define B_  8
#define T_  2048
#define C_  1024
#define H_  64
#define BT_  (B_ * T_)          // 16384
#define BTH_ (BT_ * H_)         // 1048576

// ---------------- device scratch (no allocations allowed) ----------------
__device__ __nv_bfloat16 g_W3h[192 * 1024];   // hi: rows 0-63 Wq, 64-127 E^T Wk, 128-191 F^T Wv
__device__ __nv_bfloat16 g_W3l[192 * 1024];   // lo residuals
__device__ float g_qkv[3 * BTH_];             // [Q | Kp | Vp], each [B,T,H] row-major

// ================= helpers =================
__device__ __forceinline__ uint32_t smem_u32(const void* p) {
    uint32_t a;
    asm("{ .reg .u64 t; cvta.to.shared.u64 t, %1; cvt.u32.u64 %0, t; }" : "=r"(a) : "l"(p));
    return a;
}
__device__ __forceinline__ float ex2f(float x) {
    float y;
    asm("ex2.approx.ftz.f32 %0, %1;" : "=f"(y) : "f"(x));
    return y;
}
__device__ __forceinline__ uint32_t pack_bf16(__nv_bfloat16 a, __nv_bfloat16 b) {
    __nv_bfloat162 t(a, b);
    return *reinterpret_cast<uint32_t*>(&t);
}
#define LDSM4(r, addr) \
    asm volatile("ldmatrix.sync.aligned.m8n8.x4.shared.b16 {%0,%1,%2,%3}, [%4];" \
                 : "=r"((r)[0]), "=r"((r)[1]), "=r"((r)[2]), "=r"((r)[3]) : "r"(addr))
#define MMA16816(c, a, b0, b1) \
    asm volatile("mma.sync.aligned.m16n8k16.row.col.f32.bf16.bf16.f32 " \
                 "{%0,%1,%2,%3}, {%4,%5,%6,%7}, {%8,%9}, {%0,%1,%2,%3};" \
                 : "+f"((c)[0]), "+f"((c)[1]), "+f"((c)[2]), "+f"((c)[3]) \
                 : "r"((a)[0]), "r"((a)[1]), "r"((a)[2]), "r"((a)[3]), "r"(b0), "r"(b1))

// ---------------- kernel 1: fuse E/F into K/V weights, emit bf16 hi/lo ----------------
__global__ void combine_w_kernel(const float* __restrict__ Wq, const float* __restrict__ Wk,
                                 const float* __restrict__ Wv, const float* __restrict__ E,
                                 const float* __restrict__ F) {
    int idx = blockIdx.x * 256 + threadIdx.x;     // 192*1024 total
    int n = idx >> 10, c = idx & 1023;
    float val;
    if (n < 64) {
        val = Wq[n * 1024 + c];
    } else if (n < 128) {
        int d = n - 64;
        float s = 0.f;
        #pragma unroll
        for (int h = 0; h < 64; ++h) s += E[h * 64 + d] * Wk[h * 1024 + c];
        val = s;
    } else {
        int d = n - 128;
        float s = 0.f;
        #pragma unroll
        for (int h = 0; h < 64; ++h) s += F[h * 64 + d] * Wv[h * 1024 + c];
        val = s;
    }
    __nv_bfloat16 hi = __float2bfloat16(val);
    __nv_bfloat16 lo = __float2bfloat16(val - __bfloat162float(hi));
    g_W3h[n * 1024 + c] = hi;
    g_W3l[n * 1024 + c] = lo;
}

// ---------------- kernel 2: mma.sync projection GEMM (bf16 hi/lo split) ----------------
// Y[16384][192] = x @ W3^T. CTA: 128(M) x 64(N), BK=32, 8 warps (4m x 2n), warp tile 32x32.
// Three passes per K-chunk: hi*hi + lo*hi + hi*lo, fp32 accumulators.
#define ASTRIDE 40   // bf16 elems per smem row (32 + 8 pad) -> 80B, LDSM conflict-free

__global__ __launch_bounds__(256) void proj_mma_kernel(const float* __restrict__ x) {
    __shared__ __nv_bfloat16 Ah[128 * ASTRIDE];
    __shared__ __nv_bfloat16 Al[128 * ASTRIDE];
    __shared__ __nv_bfloat16 Bh[64 * ASTRIDE];
    __shared__ __nv_bfloat16 Bl[64 * ASTRIDE];

    const int tid = threadIdx.x;
    const int lane = tid & 31, w = tid >> 5;
    const int wm = w & 3, wn = w >> 2;        // warp grid 4(m) x 2(n)
    const int m0 = blockIdx.x * 128;
    const int n0 = blockIdx.y * 64;           // weight-row block (Q/Kp/Vp)

    float c[2][4][4];                          // [m-sub16][n-blk8][4 regs]
    #pragma unroll
    for (int i = 0; i < 2; ++i)
        #pragma unroll
        for (int j = 0; j < 4; ++j)
            #pragma unroll
            for (int q = 0; q < 4; ++q) c[i][j][q] = 0.f;

    // precomputed ldmatrix smem addresses (vary only with k16 offset)
    const int arow = wm * 32 + (lane & 15);
    const int brow = wn * 32 + (lane & 15);
    const int koff = (lane >> 4) * 8;

    for (int kt = 0; kt < 1024; kt += 32) {
        __syncthreads();
        // A tile: 128x32 fp32 -> bf16 hi/lo. 1024 float4, 4 per thread.
        #pragma unroll
        for (int u = 0; u < 4; ++u) {
            int idx = tid + u * 256;
            int row = idx >> 3, c4 = (idx & 7) * 4;
            float4 v = *(const float4*)(x + (size_t)(m0 + row) * 1024 + kt + c4);
            __nv_bfloat16 h0 = __float2bfloat16(v.x), h1 = __float2bfloat16(v.y);
            __nv_bfloat16 h2 = __float2bfloat16(v.z), h3 = __float2bfloat16(v.w);
            __nv_bfloat16 l0 = __float2bfloat16(v.x - __bfloat162float(h0));
            __nv_bfloat16 l1 = __float2bfloat16(v.y - __bfloat162float(h1));
            __nv_bfloat16 l2 = __float2bfloat16(v.z - __bfloat162float(h2));
            __nv_bfloat16 l3 = __float2bfloat16(v.w - __bfloat162float(h3));
            *(uint2*)&Ah[row * ASTRIDE + c4] = make_uint2(pack_bf16(h0, h1), pack_bf16(h2, h3));
            *(uint2*)&Al[row * ASTRIDE + c4] = make_uint2(pack_bf16(l0, l1), pack_bf16(l2, l3));
        }
        // B tile: 64x32 bf16 hi/lo, one uint4 (8 bf16) per thread.
        {
            int row = tid >> 2, c8 = (tid & 3) * 8;
            size_t g = (size_t)(n0 + row) * 1024 + kt + c8;
            *(uint4*)&Bh[row * ASTRIDE + c8] = *(const uint4*)(g_W3h + g);
            *(uint4*)&Bl[row * ASTRIDE + c8] = *(const uint4*)(g_W3l + g);
        }
        __syncthreads();

        #pragma unroll
        for (int p = 0; p < 3; ++p) {
            const __nv_bfloat16* As = (p == 1) ? Al : Ah;
            const __nv_bfloat16* Bs = (p == 2) ? Bl : Bh;
            #pragma unroll
            for (int k16 = 0; k16 < 2; ++k16) {
                uint32_t a[2][4], b[2][4];
                #pragma unroll
                for (int s = 0; s < 2; ++s) {
                    LDSM4(a[s], smem_u32(&As[(arow + s * 16) * ASTRIDE + k16 * 16 + koff]));
                    LDSM4(b[s], smem_u32(&Bs[(brow + s * 16) * ASTRIDE + k16 * 16 + koff]));
                }
                #pragma unroll
                for (int ms = 0; ms < 2; ++ms)
                    #pragma unroll
                    for (int nb = 0; nb < 4; ++nb)
                        MMA16816(c[ms][nb], a[ms], b[nb >> 1][nb & 1], b[nb >> 1][(nb & 1) + 2]);
            }
        }
    }

    // epilogue: write fp32 results into g_qkv[blockIdx.y]
    float* outp = g_qkv + (size_t)blockIdx.y * BTH_;
    #pragma unroll
    for (int ms = 0; ms < 2; ++ms) {
        int r0 = m0 + wm * 32 + ms * 16 + (lane >> 2);
        #pragma unroll
        for (int nb = 0; nb < 4; ++nb) {
            int col = wn * 32 + nb * 8 + (lane & 3) * 2;
            *(float2*)(outp + (size_t)r0 * 64 + col)       = make_float2(c[ms][nb][0], c[ms][nb][1]);
            *(float2*)(outp + (size_t)(r0 + 8) * 64 + col) = make_float2(c[ms][nb][2], c[ms][nb][3]);
        }
    }
}

// ---------------- kernel 3: causal flash attention (SIMT fp32, unchanged) ----------------
#define ATTN_SMEM 114688

__global__ __launch_bounds__(128) void attn_kernel(float* __restrict__ out) {
    extern __shared__ float smf[];
    float* Qt = smf;                   // Qt[h*64 + i]
    float* Kt = Qt + 64 * 64;          // Kt[h*128 + j]
    float* Vs = Kt + 64 * 128;         // Vs[j*64 + h]
    float* Ps = Vs + 128 * 64;         // Ps[i*128 + j]

    const int b  = blockIdx.y;
    const int qt = 31 - blockIdx.x;    // descending work size (LPT)
    const int tid = threadIdx.x;
    const int tx = tid & 15;
    const int ty = tid >> 4;
    const int i0 = ty * 8;
    const int rowg0 = qt * 64;

    const float* Qg = g_qkv + ((size_t)(b * T_) + rowg0) * H_;
    const float* Kg = g_qkv + BTH_ + (size_t)(b * T_) * H_;
    const float* Vg = g_qkv + 2 * BTH_ + (size_t)(b * T_) * H_;

    const float qscale = 0.0625f * 1.4426950408889634f;
    for (int u = tid; u < 64 * 16; u += 128) {
        int row = u >> 4, h4 = (u & 15) * 4;
        float4 v = *(const float4*)(Qg + (size_t)row * 64 + h4);
        Qt[(h4 + 0) * 64 + row] = v.x * qscale;
        Qt[(h4 + 1) * 64 + row] = v.y * qscale;
        Qt[(h4 + 2) * 64 + row] = v.z * qscale;
        Qt[(h4 + 3) * 64 + row] = v.w * qscale;
    }

    float m_i[8], l_i[8], o[8][4];
    #pragma unroll
    for (int r = 0; r < 8; ++r) {
        m_i[r] = -1e30f; l_i[r] = 0.f;
        #pragma unroll
        for (int c = 0; c < 4; ++c) o[r][c] = 0.f;
    }

    const int ntiles = ((qt * 64 + 63) >> 7) + 1;
    for (int kt = 0; kt < ntiles; ++kt) {
        __syncthreads();
        const float* Kp = Kg + (size_t)kt * 128 * 64;
        const float* Vp = Vg + (size_t)kt * 128 * 64;
        for (int u = tid; u < 2048; u += 128) {
            int row = u >> 4, h4 = (u & 15) * 4;
            float4 kv = *(const float4*)(Kp + (size_t)row * 64 + h4);
            Kt[(h4 + 0) * 128 + row] = kv.x;
            Kt[(h4 + 1) * 128 + row] = kv.y;
            Kt[(h4 + 2) * 128 + row] = kv.z;
            Kt[(h4 + 3) * 128 + row] = kv.w;
            *(float4*)(Vs + (size_t)row * 64 + h4) = *(const float4*)(Vp + (size_t)row * 64 + h4);
        }
        __syncthreads();

        float s[8][8];
        #pragma unroll
        for (int r = 0; r < 8; ++r)
            #pragma unroll
            for (int c = 0; c < 8; ++c) s[r][c] = 0.f;

        #pragma unroll 8
        for (int h = 0; h < 64; ++h) {
            float4 a0 = *(const float4*)(Qt + h * 64 + i0);
            float4 a1 = *(const float4*)(Qt + h * 64 + i0 + 4);
            float4 b0 = *(const float4*)(Kt + h * 128 + tx * 8);
            float4 b1 = *(const float4*)(Kt + h * 128 + tx * 8 + 4);
            float a[8] = {a0.x, a0.y, a0.z, a0.w, a1.x, a1.y, a1.z, a1.w};
            float bb[8] = {b0.x, b0.y, b0.z, b0.w, b1.x, b1.y, b1.z, b1.w};
            #pragma unroll
            for (int r = 0; r < 8; ++r)
                #pragma unroll
                for (int c = 0; c < 8; ++c) s[r][c] += a[r] * bb[c];
        }

        if (kt * 128 + 127 > rowg0) {
            #pragma unroll
            for (int r = 0; r < 8; ++r) {
                int ig = rowg0 + i0 + r;
                #pragma unroll
                for (int c = 0; c < 8; ++c) {
                    int jg = kt * 128 + tx * 8 + c;
                    if (jg > ig) s[r][c] = -1e30f;
                }
            }
        }

        #pragma unroll
        for (int r = 0; r < 8; ++r) {
            float mx = s[r][0];
            #pragma unroll
            for (int c = 1; c < 8; ++c) mx = fmaxf(mx, s[r][c]);
            #pragma unroll
            for (int off = 1; off < 16; off <<= 1)
                mx = fmaxf(mx, __shfl_xor_sync(0xffffffffu, mx, off));
            float mnew = fmaxf(m_i[r], mx);
            float alpha = ex2f(m_i[r] - mnew);
            m_i[r] = mnew;
            l_i[r] *= alpha;
            #pragma unroll
            for (int c = 0; c < 4; ++c) o[r][c] *= alpha;
            float rs = 0.f;
            #pragma unroll
            for (int c = 0; c < 8; ++c) {
                float p = ex2f(s[r][c] - mnew);
                s[r][c] = p;
                rs += p;
            }
            #pragma unroll
            for (int off = 1; off < 16; off <<= 1)
                rs += __shfl_xor_sync(0xffffffffu, rs, off);
            l_i[r] += rs;
        }

        #pragma unroll
        for (int r = 0; r < 8; ++r) {
            *(float4*)(Ps + (i0 + r) * 128 + tx * 8)     = make_float4(s[r][0], s[r][1], s[r][2], s[r][3]);
            *(float4*)(Ps + (i0 + r) * 128 + tx * 8 + 4) = make_float4(s[r][4], s[r][5], s[r][6], s[r][7]);
        }
        __syncthreads();

        #pragma unroll 4
        for (int j = 0; j < 128; ++j) {
            float4 v = *(const float4*)(Vs + j * 64 + tx * 4);
            #pragma unroll
            for (int r = 0; r < 8; ++r) {
                float p = Ps[(i0 + r) * 128 + j];
                o[r][0] += p * v.x; o[r][1] += p * v.y;
                o[r][2] += p * v.z; o[r][3] += p * v.w;
            }
        }
    }

    #pragma unroll
    for (int r = 0; r < 8; ++r) {
        float inv = 1.0f / l_i[r];
        size_t rowglob = (size_t)b * T_ + rowg0 + i0 + r;
        float4 v = make_float4(o[r][0] * inv, o[r][1] * inv, o[r][2] * inv, o[r][3] * inv);
        *(float4*)(out + rowglob * 64 + tx * 4) = v;
    }
}

// ---------------- launch ----------------
extern "C" void kernel_launch(void* const* d_in, const int* in_sizes, int n_in,
                              void* d_out, int out_size) {
    const float* x  = (const float*)d_in[0];
    const float* Wq = (const float*)d_in[1];
    const float* Wk = (const float*)d_in[2];
    const float* Wv = (const float*)d_in[3];
    const float* E  = (const float*)d_in[4];
    const float* F  = (const float*)d_in[5];
    float* out = (float*)d_out;

    combine_w_kernel<<<(192 * 1024) / 256, 256>>>(Wq, Wk, Wv, E, F);

    dim3 g2(BT_ / 128, 3);
    proj_mma_kernel<<<g2, 256>>>(x);

    cudaFuncSetAttribute(attn_kernel, cudaFuncAttributeMaxDynamicSharedMemorySize, ATTN_SMEM);
    attn_kernel<<<dim3(32, B_), 128, ATTN_SMEM>>>(out);
}

// round 5
// speedup vs baseline: 2.1940x; 1.8948x over previous
#include <cuda_runtime.h>
#include <cuda_bf16.h>
#include <cstdint>

#define B_  8
#define T_  2048
#define C_  1024
#define H_  64
#define BT_  (B_ * T_)          // 16384
#define BTH_ (BT_ * H_)         // 1048576

// ---------------- device scratch (no allocations allowed) ----------------
__device__ __nv_bfloat16 g_W3h[192 * 1024];
__device__ __nv_bfloat16 g_W3l[192 * 1024];
// hi/lo bf16 split of projected Q (pre-scaled), Kp, Vp — [B,T,H] row-major
__device__ __nv_bfloat16 g_qh[BTH_], g_ql[BTH_];
__device__ __nv_bfloat16 g_kh[BTH_], g_kl[BTH_];
__device__ __nv_bfloat16 g_vh[BTH_], g_vl[BTH_];

// ================= helpers =================
__device__ __forceinline__ uint32_t smem_u32(const void* p) {
    uint32_t a;
    asm("{ .reg .u64 t; cvta.to.shared.u64 t, %1; cvt.u32.u64 %0, t; }" : "=r"(a) : "l"(p));
    return a;
}
__device__ __forceinline__ float ex2f(float x) {
    float y;
    asm("ex2.approx.ftz.f32 %0, %1;" : "=f"(y) : "f"(x));
    return y;
}
__device__ __forceinline__ uint32_t pack_bf16(__nv_bfloat16 a, __nv_bfloat16 b) {
    __nv_bfloat162 t(a, b);
    return *reinterpret_cast<uint32_t*>(&t);
}
// hi/lo split of two fp32 values -> packed bf16x2 hi and lo words
__device__ __forceinline__ void split2(float v0, float v1, uint32_t& h, uint32_t& l) {
    __nv_bfloat16 h0 = __float2bfloat16(v0), h1 = __float2bfloat16(v1);
    float r0 = v0 - __bfloat162float(h0), r1 = v1 - __bfloat162float(h1);
    h = pack_bf16(h0, h1);
    l = pack_bf16(__float2bfloat16(r0), __float2bfloat16(r1));
}
#define LDSM4(r, addr) \
    asm volatile("ldmatrix.sync.aligned.m8n8.x4.shared.b16 {%0,%1,%2,%3}, [%4];" \
                 : "=r"((r)[0]), "=r"((r)[1]), "=r"((r)[2]), "=r"((r)[3]) : "r"(addr))
#define LDSM4T(r, addr) \
    asm volatile("ldmatrix.sync.aligned.m8n8.x4.trans.shared.b16 {%0,%1,%2,%3}, [%4];" \
                 : "=r"((r)[0]), "=r"((r)[1]), "=r"((r)[2]), "=r"((r)[3]) : "r"(addr))
#define MMA16816(c, a, b0, b1) \
    asm volatile("mma.sync.aligned.m16n8k16.row.col.f32.bf16.bf16.f32 " \
                 "{%0,%1,%2,%3}, {%4,%5,%6,%7}, {%8,%9}, {%0,%1,%2,%3};" \
                 : "+f"((c)[0]), "+f"((c)[1]), "+f"((c)[2]), "+f"((c)[3]) \
                 : "r"((a)[0]), "r"((a)[1]), "r"((a)[2]), "r"((a)[3]), "r"(b0), "r"(b1))

// ---------------- kernel 1: fuse E/F into K/V weights, emit bf16 hi/lo ----------------
__global__ void combine_w_kernel(const float* __restrict__ Wq, const float* __restrict__ Wk,
                                 const float* __restrict__ Wv, const float* __restrict__ E,
                                 const float* __restrict__ F) {
    int idx = blockIdx.x * 256 + threadIdx.x;     // 192*1024 total
    int n = idx >> 10, c = idx & 1023;
    float val;
    if (n < 64) {
        val = Wq[n * 1024 + c];
    } else if (n < 128) {
        int d = n - 64;
        float s = 0.f;
        #pragma unroll
        for (int h = 0; h < 64; ++h) s += E[h * 64 + d] * Wk[h * 1024 + c];
        val = s;
    } else {
        int d = n - 128;
        float s = 0.f;
        #pragma unroll
        for (int h = 0; h < 64; ++h) s += F[h * 64 + d] * Wv[h * 1024 + c];
        val = s;
    }
    __nv_bfloat16 hi = __float2bfloat16(val);
    __nv_bfloat16 lo = __float2bfloat16(val - __bfloat162float(hi));
    g_W3h[n * 1024 + c] = hi;
    g_W3l[n * 1024 + c] = lo;
}

// ---------------- kernel 2: mma.sync projection GEMM (bf16 hi/lo split) ----------------
// CTA: 128(M) x 64(N), BK=32, 8 warps (4m x 2n). Epilogue emits bf16 hi/lo of results.
#define ASTRIDE 40   // 32 + 8 pad bf16 elems -> 80B rows, conflict-free LDSM

__global__ __launch_bounds__(256) void proj_mma_kernel(const float* __restrict__ x) {
    __shared__ __nv_bfloat16 Ah[128 * ASTRIDE];
    __shared__ __nv_bfloat16 Al[128 * ASTRIDE];
    __shared__ __nv_bfloat16 Bh[64 * ASTRIDE];
    __shared__ __nv_bfloat16 Bl[64 * ASTRIDE];

    const int tid = threadIdx.x;
    const int lane = tid & 31, w = tid >> 5;
    const int wm = w & 3, wn = w >> 2;
    const int m0 = blockIdx.x * 128;
    const int n0 = blockIdx.y * 64;

    float c[2][4][4];
    #pragma unroll
    for (int i = 0; i < 2; ++i)
        #pragma unroll
        for (int j = 0; j < 4; ++j)
            #pragma unroll
            for (int q = 0; q < 4; ++q) c[i][j][q] = 0.f;

    const int arow = wm * 32 + (lane & 15);
    const int brow = wn * 32 + (lane & 15);
    const int koff = (lane >> 4) * 8;

    for (int kt = 0; kt < 1024; kt += 32) {
        __syncthreads();
        #pragma unroll
        for (int u = 0; u < 4; ++u) {
            int idx = tid + u * 256;
            int row = idx >> 3, c4 = (idx & 7) * 4;
            float4 v = *(const float4*)(x + (size_t)(m0 + row) * 1024 + kt + c4);
            __nv_bfloat16 h0 = __float2bfloat16(v.x), h1 = __float2bfloat16(v.y);
            __nv_bfloat16 h2 = __float2bfloat16(v.z), h3 = __float2bfloat16(v.w);
            __nv_bfloat16 l0 = __float2bfloat16(v.x - __bfloat162float(h0));
            __nv_bfloat16 l1 = __float2bfloat16(v.y - __bfloat162float(h1));
            __nv_bfloat16 l2 = __float2bfloat16(v.z - __bfloat162float(h2));
            __nv_bfloat16 l3 = __float2bfloat16(v.w - __bfloat162float(h3));
            *(uint2*)&Ah[row * ASTRIDE + c4] = make_uint2(pack_bf16(h0, h1), pack_bf16(h2, h3));
            *(uint2*)&Al[row * ASTRIDE + c4] = make_uint2(pack_bf16(l0, l1), pack_bf16(l2, l3));
        }
        {
            int row = tid >> 2, c8 = (tid & 3) * 8;
            size_t g = (size_t)(n0 + row) * 1024 + kt + c8;
            *(uint4*)&Bh[row * ASTRIDE + c8] = *(const uint4*)(g_W3h + g);
            *(uint4*)&Bl[row * ASTRIDE + c8] = *(const uint4*)(g_W3l + g);
        }
        __syncthreads();

        #pragma unroll
        for (int p = 0; p < 3; ++p) {
            const __nv_bfloat16* As = (p == 1) ? Al : Ah;
            const __nv_bfloat16* Bs = (p == 2) ? Bl : Bh;
            #pragma unroll
            for (int k16 = 0; k16 < 2; ++k16) {
                uint32_t a[2][4], b[2][4];
                #pragma unroll
                for (int s = 0; s < 2; ++s) {
                    LDSM4(a[s], smem_u32(&As[(arow + s * 16) * ASTRIDE + k16 * 16 + koff]));
                    LDSM4(b[s], smem_u32(&Bs[(brow + s * 16) * ASTRIDE + k16 * 16 + koff]));
                }
                #pragma unroll
                for (int ms = 0; ms < 2; ++ms)
                    #pragma unroll
                    for (int nb = 0; nb < 4; ++nb)
                        MMA16816(c[ms][nb], a[ms], b[nb >> 1][nb & 1], b[nb >> 1][(nb & 1) + 2]);
            }
        }
    }

    // epilogue: hi/lo bf16 split straight to the attention operand tensors
    const float scale = (blockIdx.y == 0) ? (0.0625f * 1.4426950408889634f) : 1.0f;
    __nv_bfloat16* ph = (blockIdx.y == 0) ? g_qh : (blockIdx.y == 1 ? g_kh : g_vh);
    __nv_bfloat16* pl = (blockIdx.y == 0) ? g_ql : (blockIdx.y == 1 ? g_kl : g_vl);
    #pragma unroll
    for (int ms = 0; ms < 2; ++ms) {
        int r0 = m0 + wm * 32 + ms * 16 + (lane >> 2);
        #pragma unroll
        for (int nb = 0; nb < 4; ++nb) {
            int col = wn * 32 + nb * 8 + (lane & 3) * 2;
            uint32_t h, l;
            split2(c[ms][nb][0] * scale, c[ms][nb][1] * scale, h, l);
            *(uint32_t*)&ph[(size_t)r0 * 64 + col] = h;
            *(uint32_t*)&pl[(size_t)r0 * 64 + col] = l;
            split2(c[ms][nb][2] * scale, c[ms][nb][3] * scale, h, l);
            *(uint32_t*)&ph[(size_t)(r0 + 8) * 64 + col] = h;
            *(uint32_t*)&pl[(size_t)(r0 + 8) * 64 + col] = l;
        }
    }
}

// ---------------- kernel 3: tensor-core causal flash attention ----------------
// CTA: 64 q-rows x 128-key tiles, 4 warps (16 rows each). bf16 hi/lo 3-pass on
// both GEMMs; P kept in registers (accum frag == A frag layout).
#define QSTRIDE 72
#define SM_QH  0
#define SM_QL  (64 * QSTRIDE)
#define SM_KH  (2 * 64 * QSTRIDE)
#define SM_KL  (SM_KH + 128 * QSTRIDE)
#define SM_VH  (SM_KH + 2 * 128 * QSTRIDE)
#define SM_VL  (SM_KH + 3 * 128 * QSTRIDE)
#define ATTN_SMEM_BYTES ((2 * 64 * QSTRIDE + 4 * 128 * QSTRIDE) * 2)   // 92160

__global__ __launch_bounds__(128) void attn_mma_kernel(float* __restrict__ out) {
    extern __shared__ __nv_bfloat16 sb[];
    __nv_bfloat16* Qh = sb + SM_QH;
    __nv_bfloat16* Ql = sb + SM_QL;
    __nv_bfloat16* Kh = sb + SM_KH;
    __nv_bfloat16* Kl = sb + SM_KL;
    __nv_bfloat16* Vh = sb + SM_VH;
    __nv_bfloat16* Vl = sb + SM_VL;

    const int b = blockIdx.y;
    const int qt = 31 - blockIdx.x;       // LPT: biggest tiles first
    const int tid = threadIdx.x;
    const int lane = tid & 31, w = tid >> 5;
    const int rowg0 = qt * 64;
    const size_t qbase = ((size_t)(b * T_) + rowg0) * H_;
    const size_t kvbase = (size_t)(b * T_) * H_;

    // load Q tile (64x64 hi/lo)
    #pragma unroll
    for (int u = 0; u < 4; ++u) {
        int idx = tid + u * 128;
        int row = idx >> 3, c8 = (idx & 7) * 8;
        *(uint4*)&Qh[row * QSTRIDE + c8] = *(const uint4*)(g_qh + qbase + (size_t)row * 64 + c8);
        *(uint4*)&Ql[row * QSTRIDE + c8] = *(const uint4*)(g_ql + qbase + (size_t)row * 64 + c8);
    }

    float m0 = -1e30f, m1 = -1e30f, l0 = 0.f, l1 = 0.f;
    float o[8][4];
    #pragma unroll
    for (int i = 0; i < 8; ++i)
        #pragma unroll
        for (int q = 0; q < 4; ++q) o[i][q] = 0.f;

    const int arow = w * 16 + (lane & 15);
    const int koff = (lane >> 4) * 8;
    const int r0loc = lane >> 2;          // row within warp tile (0..7)

    const int ntiles = (qt >> 1) + 1;
    for (int kt = 0; kt < ntiles; ++kt) {
        __syncthreads();
        const size_t base = kvbase + (size_t)kt * 128 * 64;
        #pragma unroll
        for (int u = 0; u < 8; ++u) {
            int idx = tid + u * 128;
            int row = idx >> 3, c8 = (idx & 7) * 8;
            size_t g = base + (size_t)row * 64 + c8;
            *(uint4*)&Kh[row * QSTRIDE + c8] = *(const uint4*)(g_kh + g);
            *(uint4*)&Kl[row * QSTRIDE + c8] = *(const uint4*)(g_kl + g);
            *(uint4*)&Vh[row * QSTRIDE + c8] = *(const uint4*)(g_vh + g);
            *(uint4*)&Vl[row * QSTRIDE + c8] = *(const uint4*)(g_vl + g);
        }
        __syncthreads();

        // ---- S = Q @ K^T (3 passes folded: hh + lh + hl) ----
        float s[16][4];
        #pragma unroll
        for (int nb = 0; nb < 16; ++nb)
            #pragma unroll
            for (int q = 0; q < 4; ++q) s[nb][q] = 0.f;

        #pragma unroll
        for (int k16 = 0; k16 < 4; ++k16) {
            uint32_t ah[4], al[4];
            LDSM4(ah, smem_u32(&Qh[arow * QSTRIDE + k16 * 16 + koff]));
            LDSM4(al, smem_u32(&Ql[arow * QSTRIDE + k16 * 16 + koff]));
            #pragma unroll
            for (int g = 0; g < 8; ++g) {
                uint32_t bh[4], bl[4];
                LDSM4(bh, smem_u32(&Kh[(g * 16 + (lane & 15)) * QSTRIDE + k16 * 16 + koff]));
                LDSM4(bl, smem_u32(&Kl[(g * 16 + (lane & 15)) * QSTRIDE + k16 * 16 + koff]));
                MMA16816(s[2 * g],     ah, bh[0], bh[2]);
                MMA16816(s[2 * g],     al, bh[0], bh[2]);
                MMA16816(s[2 * g],     ah, bl[0], bl[2]);
                MMA16816(s[2 * g + 1], ah, bh[1], bh[3]);
                MMA16816(s[2 * g + 1], al, bh[1], bh[3]);
                MMA16816(s[2 * g + 1], ah, bl[1], bl[3]);
            }
        }

        // ---- causal mask (only the diagonal tile) ----
        if (kt == ntiles - 1) {
            int ig0 = rowg0 + w * 16 + r0loc;
            #pragma unroll
            for (int nb = 0; nb < 16; ++nb) {
                int cg = kt * 128 + nb * 8 + (lane & 3) * 2;
                if (cg > ig0)         s[nb][0] = -1e30f;
                if (cg + 1 > ig0)     s[nb][1] = -1e30f;
                if (cg > ig0 + 8)     s[nb][2] = -1e30f;
                if (cg + 1 > ig0 + 8) s[nb][3] = -1e30f;
            }
        }

        // ---- online softmax (base-2; Q pre-scaled by scale*log2e) ----
        float mx0 = -1e30f, mx1 = -1e30f;
        #pragma unroll
        for (int nb = 0; nb < 16; ++nb) {
            mx0 = fmaxf(mx0, fmaxf(s[nb][0], s[nb][1]));
            mx1 = fmaxf(mx1, fmaxf(s[nb][2], s[nb][3]));
        }
        mx0 = fmaxf(mx0, __shfl_xor_sync(0xffffffffu, mx0, 1));
        mx0 = fmaxf(mx0, __shfl_xor_sync(0xffffffffu, mx0, 2));
        mx1 = fmaxf(mx1, __shfl_xor_sync(0xffffffffu, mx1, 1));
        mx1 = fmaxf(mx1, __shfl_xor_sync(0xffffffffu, mx1, 2));
        float mn0 = fmaxf(m0, mx0), mn1 = fmaxf(m1, mx1);
        float al0 = ex2f(m0 - mn0), al1 = ex2f(m1 - mn1);
        m0 = mn0; m1 = mn1;
        #pragma unroll
        for (int i = 0; i < 8; ++i) {
            o[i][0] *= al0; o[i][1] *= al0;
            o[i][2] *= al1; o[i][3] *= al1;
        }
        float rs0 = 0.f, rs1 = 0.f;
        #pragma unroll
        for (int nb = 0; nb < 16; ++nb) {
            float p0 = ex2f(s[nb][0] - mn0); s[nb][0] = p0; rs0 += p0;
            float p1 = ex2f(s[nb][1] - mn0); s[nb][1] = p1; rs0 += p1;
            float p2 = ex2f(s[nb][2] - mn1); s[nb][2] = p2; rs1 += p2;
            float p3 = ex2f(s[nb][3] - mn1); s[nb][3] = p3; rs1 += p3;
        }
        rs0 += __shfl_xor_sync(0xffffffffu, rs0, 1);
        rs0 += __shfl_xor_sync(0xffffffffu, rs0, 2);
        rs1 += __shfl_xor_sync(0xffffffffu, rs1, 1);
        rs1 += __shfl_xor_sync(0xffffffffu, rs1, 2);
        l0 = l0 * al0 + rs0;
        l1 = l1 * al1 + rs1;

        // ---- O += P @ V (P from registers, V via ldmatrix.trans) ----
        #pragma unroll
        for (int kb = 0; kb < 8; ++kb) {
            uint32_t ph[4], pl[4];
            split2(s[2 * kb][0],     s[2 * kb][1],     ph[0], pl[0]);
            split2(s[2 * kb][2],     s[2 * kb][3],     ph[1], pl[1]);
            split2(s[2 * kb + 1][0], s[2 * kb + 1][1], ph[2], pl[2]);
            split2(s[2 * kb + 1][2], s[2 * kb + 1][3], ph[3], pl[3]);
            #pragma unroll
            for (int g = 0; g < 4; ++g) {
                uint32_t bh[4], bl[4];
                uint32_t va = smem_u32(&Vh[(kb * 16 + (lane & 15)) * QSTRIDE + g * 16 + koff]);
                uint32_t vb = smem_u32(&Vl[(kb * 16 + (lane & 15)) * QSTRIDE + g * 16 + koff]);
                LDSM4T(bh, va);
                LDSM4T(bl, vb);
                MMA16816(o[2 * g],     ph, bh[0], bh[1]);
                MMA16816(o[2 * g],     pl, bh[0], bh[1]);
                MMA16816(o[2 * g],     ph, bl[0], bl[1]);
                MMA16816(o[2 * g + 1], ph, bh[2], bh[3]);
                MMA16816(o[2 * g + 1], pl, bh[2], bh[3]);
                MMA16816(o[2 * g + 1], ph, bl[2], bl[3]);
            }
        }
    }

    // ---- epilogue: normalize and store ----
    float inv0 = 1.0f / l0, inv1 = 1.0f / l1;
    int rg = rowg0 + w * 16 + r0loc;
    float* op0 = out + ((size_t)(b * T_) + rg) * 64;
    float* op1 = op0 + 8 * 64;
    int col0 = (lane & 3) * 2;
    #pragma unroll
    for (int nbo = 0; nbo < 8; ++nbo) {
        int col = nbo * 8 + col0;
        *(float2*)(op0 + col) = make_float2(o[nbo][0] * inv0, o[nbo][1] * inv0);
        *(float2*)(op1 + col) = make_float2(o[nbo][2] * inv1, o[nbo][3] * inv1);
    }
}

// ---------------- launch ----------------
extern "C" void kernel_launch(void* const* d_in, const int* in_sizes, int n_in,
                              void* d_out, int out_size) {
    const float* x  = (const float*)d_in[0];
    const float* Wq = (const float*)d_in[1];
    const float* Wk = (const float*)d_in[2];
    const float* Wv = (const float*)d_in[3];
    const float* E  = (const float*)d_in[4];
    const float* F  = (const float*)d_in[5];
    float* out = (float*)d_out;

    combine_w_kernel<<<(192 * 1024) / 256, 256>>>(Wq, Wk, Wv, E, F);

    dim3 g2(BT_ / 128, 3);
    proj_mma_kernel<<<g2, 256>>>(x);

    cudaFuncSetAttribute(attn_mma_kernel, cudaFuncAttributeMaxDynamicSharedMemorySize, ATTN_SMEM_BYTES);
    attn_mma_kernel<<<dim3(32, B_), 128, ATTN_SMEM_BYTES>>>(out);
}

// round 6
// speedup vs baseline: 2.3392x; 1.0662x over previous
#include <cuda_runtime.h>
#include <cuda_bf16.h>
#include <cstdint>

#define B_  8
#define T_  2048
#define C_  1024
#define H_  64
#define BT_  (B_ * T_)          // 16384
#define BTH_ (BT_ * H_)         // 1048576

// ---------------- device scratch (no allocations allowed) ----------------
__device__ __nv_bfloat16 g_W3h[192 * 1024];
__device__ __nv_bfloat16 g_W3l[192 * 1024];
// hi/lo bf16 split of projected Q (pre-scaled), Kp, Vp — [B,T,H] row-major
__device__ __nv_bfloat16 g_qh[BTH_], g_ql[BTH_];
__device__ __nv_bfloat16 g_kh[BTH_], g_kl[BTH_];
__device__ __nv_bfloat16 g_vh[BTH_], g_vl[BTH_];

// ================= helpers =================
__device__ __forceinline__ uint32_t smem_u32(const void* p) {
    uint32_t a;
    asm("{ .reg .u64 t; cvta.to.shared.u64 t, %1; cvt.u32.u64 %0, t; }" : "=r"(a) : "l"(p));
    return a;
}
__device__ __forceinline__ float ex2f(float x) {
    float y;
    asm("ex2.approx.ftz.f32 %0, %1;" : "=f"(y) : "f"(x));
    return y;
}
__device__ __forceinline__ uint32_t pack_bf16(__nv_bfloat16 a, __nv_bfloat16 b) {
    __nv_bfloat162 t(a, b);
    return *reinterpret_cast<uint32_t*>(&t);
}
__device__ __forceinline__ void split2(float v0, float v1, uint32_t& h, uint32_t& l) {
    __nv_bfloat16 h0 = __float2bfloat16(v0), h1 = __float2bfloat16(v1);
    float r0 = v0 - __bfloat162float(h0), r1 = v1 - __bfloat162float(h1);
    h = pack_bf16(h0, h1);
    l = pack_bf16(__float2bfloat16(r0), __float2bfloat16(r1));
}
#define LDSM4(r, addr) \
    asm volatile("ldmatrix.sync.aligned.m8n8.x4.shared.b16 {%0,%1,%2,%3}, [%4];" \
                 : "=r"((r)[0]), "=r"((r)[1]), "=r"((r)[2]), "=r"((r)[3]) : "r"(addr))
#define LDSM4T(r, addr) \
    asm volatile("ldmatrix.sync.aligned.m8n8.x4.trans.shared.b16 {%0,%1,%2,%3}, [%4];" \
                 : "=r"((r)[0]), "=r"((r)[1]), "=r"((r)[2]), "=r"((r)[3]) : "r"(addr))
#define MMA16816(c, a, b0, b1) \
    asm volatile("mma.sync.aligned.m16n8k16.row.col.f32.bf16.bf16.f32 " \
                 "{%0,%1,%2,%3}, {%4,%5,%6,%7}, {%8,%9}, {%0,%1,%2,%3};" \
                 : "+f"((c)[0]), "+f"((c)[1]), "+f"((c)[2]), "+f"((c)[3]) \
                 : "r"((a)[0]), "r"((a)[1]), "r"((a)[2]), "r"((a)[3]), "r"(b0), "r"(b1))
#define CP_ASYNC16(dst, src) \
    asm volatile("cp.async.cg.shared.global [%0], [%1], 16;" :: "r"(dst), "l"(src))
#define CP_COMMIT() asm volatile("cp.async.commit_group;")
#define CP_WAIT(n)  asm volatile("cp.async.wait_group %0;" :: "n"(n))

// ---------------- kernel 1: fuse E/F into K/V weights, emit bf16 hi/lo ----------------
__global__ void combine_w_kernel(const float* __restrict__ Wq, const float* __restrict__ Wk,
                                 const float* __restrict__ Wv, const float* __restrict__ E,
                                 const float* __restrict__ F) {
    int idx = blockIdx.x * 256 + threadIdx.x;     // 192*1024 total
    int n = idx >> 10, c = idx & 1023;
    float val;
    if (n < 64) {
        val = Wq[n * 1024 + c];
    } else if (n < 128) {
        int d = n - 64;
        float s = 0.f;
        #pragma unroll
        for (int h = 0; h < 64; ++h) s += E[h * 64 + d] * Wk[h * 1024 + c];
        val = s;
    } else {
        int d = n - 128;
        float s = 0.f;
        #pragma unroll
        for (int h = 0; h < 64; ++h) s += F[h * 64 + d] * Wv[h * 1024 + c];
        val = s;
    }
    __nv_bfloat16 hi = __float2bfloat16(val);
    __nv_bfloat16 lo = __float2bfloat16(val - __bfloat162float(hi));
    g_W3h[n * 1024 + c] = hi;
    g_W3l[n * 1024 + c] = lo;
}

// ---------------- kernel 2: merged mma.sync projection GEMM ----------------
// CTA: 128(M) x 192(N, all of Q/K/V), BK=32, 8 warps (4m x 2n), 3 n-block loop.
// A converted ONCE per tile (was 3x). Three passes: hi*hi + lo*hi + hi*lo.
#define ASTRIDE 40   // 32 + 8 pad bf16 elems -> 80B rows, conflict-free LDSM
#define PROJ_A_ELEMS (128 * ASTRIDE)
#define PROJ_B_ELEMS (192 * ASTRIDE)
#define PROJ_SMEM_BYTES ((2 * PROJ_A_ELEMS + 2 * PROJ_B_ELEMS) * 2)   // 51200

__global__ __launch_bounds__(256) void proj_mma_kernel(const float* __restrict__ x) {
    extern __shared__ __nv_bfloat16 psm[];
    __nv_bfloat16* Ah = psm;
    __nv_bfloat16* Al = Ah + PROJ_A_ELEMS;
    __nv_bfloat16* Bh = Al + PROJ_A_ELEMS;
    __nv_bfloat16* Bl = Bh + PROJ_B_ELEMS;

    const int tid = threadIdx.x;
    const int lane = tid & 31, w = tid >> 5;
    const int wm = w & 3, wn = w >> 2;
    const int m0 = blockIdx.x * 128;

    float c[3][2][4][4];
    #pragma unroll
    for (int n = 0; n < 3; ++n)
        #pragma unroll
        for (int i = 0; i < 2; ++i)
            #pragma unroll
            for (int j = 0; j < 4; ++j)
                #pragma unroll
                for (int q = 0; q < 4; ++q) c[n][i][j][q] = 0.f;

    const int arow = wm * 32 + (lane & 15);
    const int brow = wn * 32 + (lane & 15);
    const int koff = (lane >> 4) * 8;

    for (int kt = 0; kt < 1024; kt += 32) {
        __syncthreads();
        // A tile: 128x32 fp32 -> bf16 hi/lo (converted once, reused by all 3 n-blocks)
        #pragma unroll
        for (int u = 0; u < 4; ++u) {
            int idx = tid + u * 256;
            int row = idx >> 3, c4 = (idx & 7) * 4;
            float4 v = *(const float4*)(x + (size_t)(m0 + row) * 1024 + kt + c4);
            __nv_bfloat16 h0 = __float2bfloat16(v.x), h1 = __float2bfloat16(v.y);
            __nv_bfloat16 h2 = __float2bfloat16(v.z), h3 = __float2bfloat16(v.w);
            __nv_bfloat16 l0 = __float2bfloat16(v.x - __bfloat162float(h0));
            __nv_bfloat16 l1 = __float2bfloat16(v.y - __bfloat162float(h1));
            __nv_bfloat16 l2 = __float2bfloat16(v.z - __bfloat162float(h2));
            __nv_bfloat16 l3 = __float2bfloat16(v.w - __bfloat162float(h3));
            *(uint2*)&Ah[row * ASTRIDE + c4] = make_uint2(pack_bf16(h0, h1), pack_bf16(h2, h3));
            *(uint2*)&Al[row * ASTRIDE + c4] = make_uint2(pack_bf16(l0, l1), pack_bf16(l2, l3));
        }
        // B tile: all 192 weight rows x 32, hi/lo. 768 uint4 each, 3/thread.
        #pragma unroll
        for (int u = 0; u < 3; ++u) {
            int idx = tid + u * 256;
            int row = idx >> 2, c8 = (idx & 3) * 8;
            size_t g = (size_t)row * 1024 + kt + c8;
            *(uint4*)&Bh[row * ASTRIDE + c8] = *(const uint4*)(g_W3h + g);
            *(uint4*)&Bl[row * ASTRIDE + c8] = *(const uint4*)(g_W3l + g);
        }
        __syncthreads();

        #pragma unroll
        for (int p = 0; p < 3; ++p) {
            const __nv_bfloat16* As = (p == 1) ? Al : Ah;
            const __nv_bfloat16* Bs = (p == 2) ? Bl : Bh;
            #pragma unroll
            for (int k16 = 0; k16 < 2; ++k16) {
                uint32_t a[2][4];
                #pragma unroll
                for (int s = 0; s < 2; ++s)
                    LDSM4(a[s], smem_u32(&As[(arow + s * 16) * ASTRIDE + k16 * 16 + koff]));
                #pragma unroll
                for (int nblk = 0; nblk < 3; ++nblk) {
                    uint32_t b[2][4];
                    #pragma unroll
                    for (int s = 0; s < 2; ++s)
                        LDSM4(b[s], smem_u32(&Bs[(nblk * 64 + brow + s * 16) * ASTRIDE + k16 * 16 + koff]));
                    #pragma unroll
                    for (int ms = 0; ms < 2; ++ms)
                        #pragma unroll
                        for (int nb = 0; nb < 4; ++nb)
                            MMA16816(c[nblk][ms][nb], a[ms], b[nb >> 1][nb & 1], b[nb >> 1][(nb & 1) + 2]);
                }
            }
        }
    }

    // epilogue: hi/lo bf16 split straight to the attention operand tensors
    #pragma unroll
    for (int nblk = 0; nblk < 3; ++nblk) {
        const float scale = (nblk == 0) ? (0.0625f * 1.4426950408889634f) : 1.0f;
        __nv_bfloat16* ph = (nblk == 0) ? g_qh : (nblk == 1 ? g_kh : g_vh);
        __nv_bfloat16* pl = (nblk == 0) ? g_ql : (nblk == 1 ? g_kl : g_vl);
        #pragma unroll
        for (int ms = 0; ms < 2; ++ms) {
            int r0 = m0 + wm * 32 + ms * 16 + (lane >> 2);
            #pragma unroll
            for (int nb = 0; nb < 4; ++nb) {
                int col = wn * 32 + nb * 8 + (lane & 3) * 2;
                uint32_t h, l;
                split2(c[nblk][ms][nb][0] * scale, c[nblk][ms][nb][1] * scale, h, l);
                *(uint32_t*)&ph[(size_t)r0 * 64 + col] = h;
                *(uint32_t*)&pl[(size_t)r0 * 64 + col] = l;
                split2(c[nblk][ms][nb][2] * scale, c[nblk][ms][nb][3] * scale, h, l);
                *(uint32_t*)&ph[(size_t)(r0 + 8) * 64 + col] = h;
                *(uint32_t*)&pl[(size_t)(r0 + 8) * 64 + col] = l;
            }
        }
    }
}

// ---------------- kernel 3: tensor-core causal flash attention ----------------
// CTA: 128 q-rows x 128-key tiles, 8 warps (16 rows each).
// K/V double-buffered via cp.async; P register-resident; bf16 hi/lo 3-pass GEMMs.
#define QSTRIDE 72
#define TEN_ELEMS (128 * QSTRIDE)                 // one 128x64(+pad) bf16 tensor
#define SM_Q_BYTES (2 * TEN_ELEMS * 2)
#define STAGE_ELEMS (4 * TEN_ELEMS)               // Kh,Kl,Vh,Vl
#define ATTN_SMEM_BYTES ((2 * TEN_ELEMS + 2 * STAGE_ELEMS) * 2)   // 184320

__global__ __launch_bounds__(256) void attn_mma_kernel(float* __restrict__ out) {
    extern __shared__ __nv_bfloat16 sb[];
    __nv_bfloat16* Qh = sb;
    __nv_bfloat16* Ql = sb + TEN_ELEMS;
    __nv_bfloat16* Stg = sb + 2 * TEN_ELEMS;      // [2][4][TEN_ELEMS]

    const int b = blockIdx.y;
    const int qt = 15 - blockIdx.x;               // LPT: biggest q-tiles first
    const int tid = threadIdx.x;
    const int lane = tid & 31, w = tid >> 5;
    const int rowg0 = qt * 128;
    const size_t qbase = ((size_t)(b * T_) + rowg0) * H_;
    const size_t kvbase = (size_t)(b * T_) * H_;

    // load Q tile (128x64 hi/lo) — plain loads, covered by first syncthreads
    #pragma unroll
    for (int u = 0; u < 4; ++u) {
        int idx = tid + u * 256;
        int row = idx >> 3, c8 = (idx & 7) * 8;
        *(uint4*)&Qh[row * QSTRIDE + c8] = *(const uint4*)(g_qh + qbase + (size_t)row * 64 + c8);
        *(uint4*)&Ql[row * QSTRIDE + c8] = *(const uint4*)(g_ql + qbase + (size_t)row * 64 + c8);
    }

    const __nv_bfloat16* gsrc[4] = {g_kh, g_kl, g_vh, g_vl};

    // prefetch helper: 4 tensors x 1024 uint4, 16 cp.async per thread
    auto prefetch = [&](int stg, int kt) {
        __nv_bfloat16* dst = Stg + stg * STAGE_ELEMS;
        size_t base = kvbase + (size_t)kt * 128 * 64;
        #pragma unroll
        for (int t = 0; t < 4; ++t) {
            #pragma unroll
            for (int u = 0; u < 4; ++u) {
                int idx = tid + u * 256;
                int row = idx >> 3, c8 = (idx & 7) * 8;
                CP_ASYNC16(smem_u32(&dst[t * TEN_ELEMS + row * QSTRIDE + c8]),
                           gsrc[t] + base + (size_t)row * 64 + c8);
            }
        }
    };

    prefetch(0, 0);
    CP_COMMIT();

    float m0 = -1e30f, m1 = -1e30f, l0 = 0.f, l1 = 0.f;
    float o[8][4];
    #pragma unroll
    for (int i = 0; i < 8; ++i)
        #pragma unroll
        for (int q = 0; q < 4; ++q) o[i][q] = 0.f;

    const int arow = w * 16 + (lane & 15);
    const int koff = (lane >> 4) * 8;
    const int r0loc = lane >> 2;

    const int ntiles = qt + 1;
    for (int kt = 0; kt < ntiles; ++kt) {
        // issue next prefetch into the stage freed at end of iter kt-1
        if (kt + 1 < ntiles) {
            prefetch((kt + 1) & 1, kt + 1);
            CP_COMMIT();
            CP_WAIT(1);                 // wait for stage kt's group
        } else {
            CP_WAIT(0);
        }
        __syncthreads();

        const __nv_bfloat16* Kh = Stg + (kt & 1) * STAGE_ELEMS;
        const __nv_bfloat16* Kl = Kh + TEN_ELEMS;
        const __nv_bfloat16* Vh = Kh + 2 * TEN_ELEMS;
        const __nv_bfloat16* Vl = Kh + 3 * TEN_ELEMS;

        // ---- S = Q @ K^T (hh + lh + hl) ----
        float s[16][4];
        #pragma unroll
        for (int nb = 0; nb < 16; ++nb)
            #pragma unroll
            for (int q = 0; q < 4; ++q) s[nb][q] = 0.f;

        #pragma unroll
        for (int k16 = 0; k16 < 4; ++k16) {
            uint32_t ah[4], al[4];
            LDSM4(ah, smem_u32(&Qh[arow * QSTRIDE + k16 * 16 + koff]));
            LDSM4(al, smem_u32(&Ql[arow * QSTRIDE + k16 * 16 + koff]));
            #pragma unroll
            for (int g = 0; g < 8; ++g) {
                uint32_t bh[4], bl[4];
                LDSM4(bh, smem_u32(&Kh[(g * 16 + (lane & 15)) * QSTRIDE + k16 * 16 + koff]));
                LDSM4(bl, smem_u32(&Kl[(g * 16 + (lane & 15)) * QSTRIDE + k16 * 16 + koff]));
                MMA16816(s[2 * g],     ah, bh[0], bh[2]);
                MMA16816(s[2 * g],     al, bh[0], bh[2]);
                MMA16816(s[2 * g],     ah, bl[0], bl[2]);
                MMA16816(s[2 * g + 1], ah, bh[1], bh[3]);
                MMA16816(s[2 * g + 1], al, bh[1], bh[3]);
                MMA16816(s[2 * g + 1], ah, bl[1], bl[3]);
            }
        }

        // ---- causal mask (diagonal tile only) ----
        if (kt == ntiles - 1) {
            int ig0 = rowg0 + w * 16 + r0loc;
            #pragma unroll
            for (int nb = 0; nb < 16; ++nb) {
                int cg = kt * 128 + nb * 8 + (lane & 3) * 2;
                if (cg > ig0)         s[nb][0] = -1e30f;
                if (cg + 1 > ig0)     s[nb][1] = -1e30f;
                if (cg > ig0 + 8)     s[nb][2] = -1e30f;
                if (cg + 1 > ig0 + 8) s[nb][3] = -1e30f;
            }
        }

        // ---- online softmax (base-2) ----
        float mx0 = -1e30f, mx1 = -1e30f;
        #pragma unroll
        for (int nb = 0; nb < 16; ++nb) {
            mx0 = fmaxf(mx0, fmaxf(s[nb][0], s[nb][1]));
            mx1 = fmaxf(mx1, fmaxf(s[nb][2], s[nb][3]));
        }
        mx0 = fmaxf(mx0, __shfl_xor_sync(0xffffffffu, mx0, 1));
        mx0 = fmaxf(mx0, __shfl_xor_sync(0xffffffffu, mx0, 2));
        mx1 = fmaxf(mx1, __shfl_xor_sync(0xffffffffu, mx1, 1));
        mx1 = fmaxf(mx1, __shfl_xor_sync(0xffffffffu, mx1, 2));
        float mn0 = fmaxf(m0, mx0), mn1 = fmaxf(m1, mx1);
        float al0 = ex2f(m0 - mn0), al1 = ex2f(m1 - mn1);
        m0 = mn0; m1 = mn1;
        #pragma unroll
        for (int i = 0; i < 8; ++i) {
            o[i][0] *= al0; o[i][1] *= al0;
            o[i][2] *= al1; o[i][3] *= al1;
        }
        float rs0 = 0.f, rs1 = 0.f;
        #pragma unroll
        for (int nb = 0; nb < 16; ++nb) {
            float p0 = ex2f(s[nb][0] - mn0); s[nb][0] = p0; rs0 += p0;
            float p1 = ex2f(s[nb][1] - mn0); s[nb][1] = p1; rs0 += p1;
            float p2 = ex2f(s[nb][2] - mn1); s[nb][2] = p2; rs1 += p2;
            float p3 = ex2f(s[nb][3] - mn1); s[nb][3] = p3; rs1 += p3;
        }
        rs0 += __shfl_xor_sync(0xffffffffu, rs0, 1);
        rs0 += __shfl_xor_sync(0xffffffffu, rs0, 2);
        rs1 += __shfl_xor_sync(0xffffffffu, rs1, 1);
        rs1 += __shfl_xor_sync(0xffffffffu, rs1, 2);
        l0 = l0 * al0 + rs0;
        l1 = l1 * al1 + rs1;

        // ---- O += P @ V (P register-resident, V via ldmatrix.trans) ----
        #pragma unroll
        for (int kb = 0; kb < 8; ++kb) {
            uint32_t ph[4], pl[4];
            split2(s[2 * kb][0],     s[2 * kb][1],     ph[0], pl[0]);
            split2(s[2 * kb][2],     s[2 * kb][3],     ph[1], pl[1]);
            split2(s[2 * kb + 1][0], s[2 * kb + 1][1], ph[2], pl[2]);
            split2(s[2 * kb + 1][2], s[2 * kb + 1][3], ph[3], pl[3]);
            #pragma unroll
            for (int g = 0; g < 4; ++g) {
                uint32_t bh[4], bl[4];
                LDSM4T(bh, smem_u32(&Vh[(kb * 16 + (lane & 15)) * QSTRIDE + g * 16 + koff]));
                LDSM4T(bl, smem_u32(&Vl[(kb * 16 + (lane & 15)) * QSTRIDE + g * 16 + koff]));
                MMA16816(o[2 * g],     ph, bh[0], bh[1]);
                MMA16816(o[2 * g],     pl, bh[0], bh[1]);
                MMA16816(o[2 * g],     ph, bl[0], bl[1]);
                MMA16816(o[2 * g + 1], ph, bh[2], bh[3]);
                MMA16816(o[2 * g + 1], pl, bh[2], bh[3]);
                MMA16816(o[2 * g + 1], ph, bl[2], bl[3]);
            }
        }
        __syncthreads();   // everyone done reading this stage before it is overwritten
    }

    // ---- epilogue: normalize and store ----
    float inv0 = 1.0f / l0, inv1 = 1.0f / l1;
    int rg = rowg0 + w * 16 + r0loc;
    float* op0 = out + ((size_t)(b * T_) + rg) * 64;
    float* op1 = op0 + 8 * 64;
    int col0 = (lane & 3) * 2;
    #pragma unroll
    for (int nbo = 0; nbo < 8; ++nbo) {
        int col = nbo * 8 + col0;
        *(float2*)(op0 + col) = make_float2(o[nbo][0] * inv0, o[nbo][1] * inv0);
        *(float2*)(op1 + col) = make_float2(o[nbo][2] * inv1, o[nbo][3] * inv1);
    }
}

// ---------------- launch ----------------
extern "C" void kernel_launch(void* const* d_in, const int* in_sizes, int n_in,
                              void* d_out, int out_size) {
    const float* x  = (const float*)d_in[0];
    const float* Wq = (const float*)d_in[1];
    const float* Wk = (const float*)d_in[2];
    const float* Wv = (const float*)d_in[3];
    const float* E  = (const float*)d_in[4];
    const float* F  = (const float*)d_in[5];
    float* out = (float*)d_out;

    combine_w_kernel<<<(192 * 1024) / 256, 256>>>(Wq, Wk, Wv, E, F);

    cudaFuncSetAttribute(proj_mma_kernel, cudaFuncAttributeMaxDynamicSharedMemorySize, PROJ_SMEM_BYTES);
    proj_mma_kernel<<<BT_ / 128, 256, PROJ_SMEM_BYTES>>>(x);

    cudaFuncSetAttribute(attn_mma_kernel, cudaFuncAttributeMaxDynamicSharedMemorySize, ATTN_SMEM_BYTES);
    attn_mma_kernel<<<dim3(16, B_), 256, ATTN_SMEM_BYTES>>>(out);
}

// round 7
// speedup vs baseline: 2.3671x; 1.0119x over previous
#include <cuda_runtime.h>
#include <cuda_bf16.h>
#include <cstdint>

#define B_  8
#define T_  2048
#define C_  1024
#define H_  64
#define BT_  (B_ * T_)          // 16384
#define BTH_ (BT_ * H_)         // 1048576

// ---------------- device scratch (no allocations allowed) ----------------
__device__ __nv_bfloat16 g_W3h[192 * 1024];
__device__ __nv_bfloat16 g_W3l[192 * 1024];
// hi/lo bf16 split of projected Q (pre-scaled), Kp, Vp — [B,T,H] row-major
__device__ __nv_bfloat16 g_qh[BTH_], g_ql[BTH_];
__device__ __nv_bfloat16 g_kh[BTH_], g_kl[BTH_];
__device__ __nv_bfloat16 g_vh[BTH_], g_vl[BTH_];

// ================= helpers =================
__device__ __forceinline__ uint32_t smem_u32(const void* p) {
    uint32_t a;
    asm("{ .reg .u64 t; cvta.to.shared.u64 t, %1; cvt.u32.u64 %0, t; }" : "=r"(a) : "l"(p));
    return a;
}
__device__ __forceinline__ float ex2f(float x) {
    float y;
    asm("ex2.approx.ftz.f32 %0, %1;" : "=f"(y) : "f"(x));
    return y;
}
__device__ __forceinline__ uint32_t pack_bf16(__nv_bfloat16 a, __nv_bfloat16 b) {
    __nv_bfloat162 t(a, b);
    return *reinterpret_cast<uint32_t*>(&t);
}
__device__ __forceinline__ void split2(float v0, float v1, uint32_t& h, uint32_t& l) {
    __nv_bfloat16 h0 = __float2bfloat16(v0), h1 = __float2bfloat16(v1);
    float r0 = v0 - __bfloat162float(h0), r1 = v1 - __bfloat162float(h1);
    h = pack_bf16(h0, h1);
    l = pack_bf16(__float2bfloat16(r0), __float2bfloat16(r1));
}
#define LDSM4(r, addr) \
    asm volatile("ldmatrix.sync.aligned.m8n8.x4.shared.b16 {%0,%1,%2,%3}, [%4];" \
                 : "=r"((r)[0]), "=r"((r)[1]), "=r"((r)[2]), "=r"((r)[3]) : "r"(addr))
#define LDSM4T(r, addr) \
    asm volatile("ldmatrix.sync.aligned.m8n8.x4.trans.shared.b16 {%0,%1,%2,%3}, [%4];" \
                 : "=r"((r)[0]), "=r"((r)[1]), "=r"((r)[2]), "=r"((r)[3]) : "r"(addr))
#define MMA16816(c, a, b0, b1) \
    asm volatile("mma.sync.aligned.m16n8k16.row.col.f32.bf16.bf16.f32 " \
                 "{%0,%1,%2,%3}, {%4,%5,%6,%7}, {%8,%9}, {%0,%1,%2,%3};" \
                 : "+f"((c)[0]), "+f"((c)[1]), "+f"((c)[2]), "+f"((c)[3]) \
                 : "r"((a)[0]), "r"((a)[1]), "r"((a)[2]), "r"((a)[3]), "r"(b0), "r"(b1))
#define CP_ASYNC16(dst, src) \
    asm volatile("cp.async.cg.shared.global [%0], [%1], 16;" :: "r"(dst), "l"(src))
#define CP_COMMIT() asm volatile("cp.async.commit_group;")
#define CP_WAIT(n)  asm volatile("cp.async.wait_group %0;" :: "n"(n))

// ---------------- kernel 1: fuse E/F into K/V weights, emit bf16 hi/lo ----------------
__global__ void combine_w_kernel(const float* __restrict__ Wq, const float* __restrict__ Wk,
                                 const float* __restrict__ Wv, const float* __restrict__ E,
                                 const float* __restrict__ F) {
    int idx = blockIdx.x * 256 + threadIdx.x;     // 192*1024 total
    int n = idx >> 10, c = idx & 1023;
    float val;
    if (n < 64) {
        val = Wq[n * 1024 + c];
    } else if (n < 128) {
        int d = n - 64;
        float s = 0.f;
        #pragma unroll
        for (int h = 0; h < 64; ++h) s += E[h * 64 + d] * Wk[h * 1024 + c];
        val = s;
    } else {
        int d = n - 128;
        float s = 0.f;
        #pragma unroll
        for (int h = 0; h < 64; ++h) s += F[h * 64 + d] * Wv[h * 1024 + c];
        val = s;
    }
    __nv_bfloat16 hi = __float2bfloat16(val);
    __nv_bfloat16 lo = __float2bfloat16(val - __bfloat162float(hi));
    g_W3h[n * 1024 + c] = hi;
    g_W3l[n * 1024 + c] = lo;
}

// ---------------- kernel 2: merged mma.sync projection GEMM ----------------
// CTA: 128(M) x 192(N, all of Q/K/V), BK=32, 8 warps (4m x 2n), 3 n-block loop.
// A converted ONCE per tile (was 3x). Three passes: hi*hi + lo*hi + hi*lo.
#define ASTRIDE 40   // 32 + 8 pad bf16 elems -> 80B rows, conflict-free LDSM
#define PROJ_A_ELEMS (128 * ASTRIDE)
#define PROJ_B_ELEMS (192 * ASTRIDE)
#define PROJ_SMEM_BYTES ((2 * PROJ_A_ELEMS + 2 * PROJ_B_ELEMS) * 2)   // 51200

__global__ __launch_bounds__(256) void proj_mma_kernel(const float* __restrict__ x) {
    extern __shared__ __nv_bfloat16 psm[];
    __nv_bfloat16* Ah = psm;
    __nv_bfloat16* Al = Ah + PROJ_A_ELEMS;
    __nv_bfloat16* Bh = Al + PROJ_A_ELEMS;
    __nv_bfloat16* Bl = Bh + PROJ_B_ELEMS;

    const int tid = threadIdx.x;
    const int lane = tid & 31, w = tid >> 5;
    const int wm = w & 3, wn = w >> 2;
    const int m0 = blockIdx.x * 128;

    float c[3][2][4][4];
    #pragma unroll
    for (int n = 0; n < 3; ++n)
        #pragma unroll
        for (int i = 0; i < 2; ++i)
            #pragma unroll
            for (int j = 0; j < 4; ++j)
                #pragma unroll
                for (int q = 0; q < 4; ++q) c[n][i][j][q] = 0.f;

    const int arow = wm * 32 + (lane & 15);
    const int brow = wn * 32 + (lane & 15);
    const int koff = (lane >> 4) * 8;

    for (int kt = 0; kt < 1024; kt += 32) {
        __syncthreads();
        // A tile: 128x32 fp32 -> bf16 hi/lo (converted once, reused by all 3 n-blocks)
        #pragma unroll
        for (int u = 0; u < 4; ++u) {
            int idx = tid + u * 256;
            int row = idx >> 3, c4 = (idx & 7) * 4;
            float4 v = *(const float4*)(x + (size_t)(m0 + row) * 1024 + kt + c4);
            __nv_bfloat16 h0 = __float2bfloat16(v.x), h1 = __float2bfloat16(v.y);
            __nv_bfloat16 h2 = __float2bfloat16(v.z), h3 = __float2bfloat16(v.w);
            __nv_bfloat16 l0 = __float2bfloat16(v.x - __bfloat162float(h0));
            __nv_bfloat16 l1 = __float2bfloat16(v.y - __bfloat162float(h1));
            __nv_bfloat16 l2 = __float2bfloat16(v.z - __bfloat162float(h2));
            __nv_bfloat16 l3 = __float2bfloat16(v.w - __bfloat162float(h3));
            *(uint2*)&Ah[row * ASTRIDE + c4] = make_uint2(pack_bf16(h0, h1), pack_bf16(h2, h3));
            *(uint2*)&Al[row * ASTRIDE + c4] = make_uint2(pack_bf16(l0, l1), pack_bf16(l2, l3));
        }
        // B tile: all 192 weight rows x 32, hi/lo. 768 uint4 each, 3/thread.
        #pragma unroll
        for (int u = 0; u < 3; ++u) {
            int idx = tid + u * 256;
            int row = idx >> 2, c8 = (idx & 3) * 8;
            size_t g = (size_t)row * 1024 + kt + c8;
            *(uint4*)&Bh[row * ASTRIDE + c8] = *(const uint4*)(g_W3h + g);
            *(uint4*)&Bl[row * ASTRIDE + c8] = *(const uint4*)(g_W3l + g);
        }
        __syncthreads();

        #pragma unroll
        for (int p = 0; p < 3; ++p) {
            const __nv_bfloat16* As = (p == 1) ? Al : Ah;
            const __nv_bfloat16* Bs = (p == 2) ? Bl : Bh;
            #pragma unroll
            for (int k16 = 0; k16 < 2; ++k16) {
                uint32_t a[2][4];
                #pragma unroll
                for (int s = 0; s < 2; ++s)
                    LDSM4(a[s], smem_u32(&As[(arow + s * 16) * ASTRIDE + k16 * 16 + koff]));
                #pragma unroll
                for (int nblk = 0; nblk < 3; ++nblk) {
                    uint32_t b[2][4];
                    #pragma unroll
                    for (int s = 0; s < 2; ++s)
                        LDSM4(b[s], smem_u32(&Bs[(nblk * 64 + brow + s * 16) * ASTRIDE + k16 * 16 + koff]));
                    #pragma unroll
                    for (int ms = 0; ms < 2; ++ms)
                        #pragma unroll
                        for (int nb = 0; nb < 4; ++nb)
                            MMA16816(c[nblk][ms][nb], a[ms], b[nb >> 1][nb & 1], b[nb >> 1][(nb & 1) + 2]);
                }
            }
        }
    }

    // epilogue: hi/lo bf16 split straight to the attention operand tensors
    #pragma unroll
    for (int nblk = 0; nblk < 3; ++nblk) {
        const float scale = (nblk == 0) ? (0.0625f * 1.4426950408889634f) : 1.0f;
        __nv_bfloat16* ph = (nblk == 0) ? g_qh : (nblk == 1 ? g_kh : g_vh);
        __nv_bfloat16* pl = (nblk == 0) ? g_ql : (nblk == 1 ? g_kl : g_vl);
        #pragma unroll
        for (int ms = 0; ms < 2; ++ms) {
            int r0 = m0 + wm * 32 + ms * 16 + (lane >> 2);
            #pragma unroll
            for (int nb = 0; nb < 4; ++nb) {
                int col = wn * 32 + nb * 8 + (lane & 3) * 2;
                uint32_t h, l;
                split2(c[nblk][ms][nb][0] * scale, c[nblk][ms][nb][1] * scale, h, l);
                *(uint32_t*)&ph[(size_t)r0 * 64 + col] = h;
                *(uint32_t*)&pl[(size_t)r0 * 64 + col] = l;
                split2(c[nblk][ms][nb][2] * scale, c[nblk][ms][nb][3] * scale, h, l);
                *(uint32_t*)&ph[(size_t)(r0 + 8) * 64 + col] = h;
                *(uint32_t*)&pl[(size_t)(r0 + 8) * 64 + col] = l;
            }
        }
    }
}

// ---------------- kernel 3: tensor-core causal flash attention ----------------
// CTA: 128 q-rows x 128-key tiles, 8 warps (16 rows each).
// K/V double-buffered via cp.async; P register-resident; bf16 hi/lo 3-pass GEMMs.
#define QSTRIDE 72
#define TEN_ELEMS (128 * QSTRIDE)                 // one 128x64(+pad) bf16 tensor
#define SM_Q_BYTES (2 * TEN_ELEMS * 2)
#define STAGE_ELEMS (4 * TEN_ELEMS)               // Kh,Kl,Vh,Vl
#define ATTN_SMEM_BYTES ((2 * TEN_ELEMS + 2 * STAGE_ELEMS) * 2)   // 184320

__global__ __launch_bounds__(256) void attn_mma_kernel(float* __restrict__ out) {
    extern __shared__ __nv_bfloat16 sb[];
    __nv_bfloat16* Qh = sb;
    __nv_bfloat16* Ql = sb + TEN_ELEMS;
    __nv_bfloat16* Stg = sb + 2 * TEN_ELEMS;      // [2][4][TEN_ELEMS]

    const int b = blockIdx.y;
    const int qt = 15 - blockIdx.x;               // LPT: biggest q-tiles first
    const int tid = threadIdx.x;
    const int lane = tid & 31, w = tid >> 5;
    const int rowg0 = qt * 128;
    const size_t qbase = ((size_t)(b * T_) + rowg0) * H_;
    const size_t kvbase = (size_t)(b * T_) * H_;

    // load Q tile (128x64 hi/lo) — plain loads, covered by first syncthreads
    #pragma unroll
    for (int u = 0; u < 4; ++u) {
        int idx = tid + u * 256;
        int row = idx >> 3, c8 = (idx & 7) * 8;
        *(uint4*)&Qh[row * QSTRIDE + c8] = *(const uint4*)(g_qh + qbase + (size_t)row * 64 + c8);
        *(uint4*)&Ql[row * QSTRIDE + c8] = *(const uint4*)(g_ql + qbase + (size_t)row * 64 + c8);
    }

    const __nv_bfloat16* gsrc[4] = {g_kh, g_kl, g_vh, g_vl};

    // prefetch helper: 4 tensors x 1024 uint4, 16 cp.async per thread
    auto prefetch = [&](int stg, int kt) {
        __nv_bfloat16* dst = Stg + stg * STAGE_ELEMS;
        size_t base = kvbase + (size_t)kt * 128 * 64;
        #pragma unroll
        for (int t = 0; t < 4; ++t) {
            #pragma unroll
            for (int u = 0; u < 4; ++u) {
                int idx = tid + u * 256;
                int row = idx >> 3, c8 = (idx & 7) * 8;
                CP_ASYNC16(smem_u32(&dst[t * TEN_ELEMS + row * QSTRIDE + c8]),
                           gsrc[t] + base + (size_t)row * 64 + c8);
            }
        }
    };

    prefetch(0, 0);
    CP_COMMIT();

    float m0 = -1e30f, m1 = -1e30f, l0 = 0.f, l1 = 0.f;
    float o[8][4];
    #pragma unroll
    for (int i = 0; i < 8; ++i)
        #pragma unroll
        for (int q = 0; q < 4; ++q) o[i][q] = 0.f;

    const int arow = w * 16 + (lane & 15);
    const int koff = (lane >> 4) * 8;
    const int r0loc = lane >> 2;

    const int ntiles = qt + 1;
    for (int kt = 0; kt < ntiles; ++kt) {
        // issue next prefetch into the stage freed at end of iter kt-1
        if (kt + 1 < ntiles) {
            prefetch((kt + 1) & 1, kt + 1);
            CP_COMMIT();
            CP_WAIT(1);                 // wait for stage kt's group
        } else {
            CP_WAIT(0);
        }
        __syncthreads();

        const __nv_bfloat16* Kh = Stg + (kt & 1) * STAGE_ELEMS;
        const __nv_bfloat16* Kl = Kh + TEN_ELEMS;
        const __nv_bfloat16* Vh = Kh + 2 * TEN_ELEMS;
        const __nv_bfloat16* Vl = Kh + 3 * TEN_ELEMS;

        // ---- S = Q @ K^T (hh + lh + hl) ----
        float s[16][4];
        #pragma unroll
        for (int nb = 0; nb < 16; ++nb)
            #pragma unroll
            for (int q = 0; q < 4; ++q) s[nb][q] = 0.f;

        #pragma unroll
        for (int k16 = 0; k16 < 4; ++k16) {
            uint32_t ah[4], al[4];
            LDSM4(ah, smem_u32(&Qh[arow * QSTRIDE + k16 * 16 + koff]));
            LDSM4(al, smem_u32(&Ql[arow * QSTRIDE + k16 * 16 + koff]));
            #pragma unroll
            for (int g = 0; g < 8; ++g) {
                uint32_t bh[4], bl[4];
                LDSM4(bh, smem_u32(&Kh[(g * 16 + (lane & 15)) * QSTRIDE + k16 * 16 + koff]));
                LDSM4(bl, smem_u32(&Kl[(g * 16 + (lane & 15)) * QSTRIDE + k16 * 16 + koff]));
                MMA16816(s[2 * g],     ah, bh[0], bh[2]);
                MMA16816(s[2 * g],     al, bh[0], bh[2]);
                MMA16816(s[2 * g],     ah, bl[0], bl[2]);
                MMA16816(s[2 * g + 1], ah, bh[1], bh[3]);
                MMA16816(s[2 * g + 1], al, bh[1], bh[3]);
                MMA16816(s[2 * g + 1], ah, bl[1], bl[3]);
            }
        }

        // ---- causal mask (diagonal tile only) ----
        if (kt == ntiles - 1) {
            int ig0 = rowg0 + w * 16 + r0loc;
            #pragma unroll
            for (int nb = 0; nb < 16; ++nb) {
                int cg = kt * 128 + nb * 8 + (lane & 3) * 2;
                if (cg > ig0)         s[nb][0] = -1e30f;
                if (cg + 1 > ig0)     s[nb][1] = -1e30f;
                if (cg > ig0 + 8)     s[nb][2] = -1e30f;
                if (cg + 1 > ig0 + 8) s[nb][3] = -1e30f;
            }
        }

        // ---- online softmax (base-2) ----
        float mx0 = -1e30f, mx1 = -1e30f;
        #pragma unroll
        for (int nb = 0; nb < 16; ++nb) {
            mx0 = fmaxf(mx0, fmaxf(s[nb][0], s[nb][1]));
            mx1 = fmaxf(mx1, fmaxf(s[nb][2], s[nb][3]));
        }
        mx0 = fmaxf(mx0, __shfl_xor_sync(0xffffffffu, mx0, 1));
        mx0 = fmaxf(mx0, __shfl_xor_sync(0xffffffffu, mx0, 2));
        mx1 = fmaxf(mx1, __shfl_xor_sync(0xffffffffu, mx1, 1));
        mx1 = fmaxf(mx1, __shfl_xor_sync(0xffffffffu, mx1, 2));
        float mn0 = fmaxf(m0, mx0), mn1 = fmaxf(m1, mx1);
        float al0 = ex2f(m0 - mn0), al1 = ex2f(m1 - mn1);
        m0 = mn0; m1 = mn1;
        #pragma unroll
        for (int i = 0; i < 8; ++i) {
            o[i][0] *= al0; o[i][1] *= al0;
            o[i][2] *= al1; o[i][3] *= al1;
        }
        float rs0 = 0.f, rs1 = 0.f;
        #pragma unroll
        for (int nb = 0; nb < 16; ++nb) {
            float p0 = ex2f(s[nb][0] - mn0); s[nb][0] = p0; rs0 += p0;
            float p1 = ex2f(s[nb][1] - mn0); s[nb][1] = p1; rs0 += p1;
            float p2 = ex2f(s[nb][2] - mn1); s[nb][2] = p2; rs1 += p2;
            float p3 = ex2f(s[nb][3] - mn1); s[nb][3] = p3; rs1 += p3;
        }
        rs0 += __shfl_xor_sync(0xffffffffu, rs0, 1);
        rs0 += __shfl_xor_sync(0xffffffffu, rs0, 2);
        rs1 += __shfl_xor_sync(0xffffffffu, rs1, 1);
        rs1 += __shfl_xor_sync(0xffffffffu, rs1, 2);
        l0 = l0 * al0 + rs0;
        l1 = l1 * al1 + rs1;

        // ---- O += P @ V (P register-resident, V via ldmatrix.trans) ----
        #pragma unroll
        for (int kb = 0; kb < 8; ++kb) {
            uint32_t ph[4], pl[4];
            split2(s[2 * kb][0],     s[2 * kb][1],     ph[0], pl[0]);
            split2(s[2 * kb][2],     s[2 * kb][3],     ph[1], pl[1]);
            split2(s[2 * kb + 1][0], s[2 * kb + 1][1], ph[2], pl[2]);
            split2(s[2 * kb + 1][2], s[2 * kb + 1][3], ph[3], pl[3]);
            #pragma unroll
            for (int g = 0; g < 4; ++g) {
                uint32_t bh[4], bl[4];
                LDSM4T(bh, smem_u32(&Vh[(kb * 16 + (lane & 15)) * QSTRIDE + g * 16 + koff]));
                LDSM4T(bl, smem_u32(&Vl[(kb * 16 + (lane & 15)) * QSTRIDE + g * 16 + koff]));
                MMA16816(o[2 * g],     ph, bh[0], bh[1]);
                MMA16816(o[2 * g],     pl, bh[0], bh[1]);
                MMA16816(o[2 * g],     ph, bl[0], bl[1]);
                MMA16816(o[2 * g + 1], ph, bh[2], bh[3]);
                MMA16816(o[2 * g + 1], pl, bh[2], bh[3]);
                MMA16816(o[2 * g + 1], ph, bl[2], bl[3]);
            }
        }
        __syncthreads();   // everyone done reading this stage before it is overwritten
    }

    // ---- epilogue: normalize and store ----
    float inv0 = 1.0f / l0, inv1 = 1.0f / l1;
    int rg = rowg0 + w * 16 + r0loc;
    float* op0 = out + ((size_t)(b * T_) + rg) * 64;
    float* op1 = op0 + 8 * 64;
    int col0 = (lane & 3) * 2;
    #pragma unroll
    for (int nbo = 0; nbo < 8; ++nbo) {
        int col = nbo * 8 + col0;
        *(float2*)(op0 + col) = make_float2(o[nbo][0] * inv0, o[nbo][1] * inv0);
        *(float2*)(op1 + col) = make_float2(o[nbo][2] * inv1, o[nbo][3] * inv1);
    }
}

// ---------------- launch ----------------
extern "C" void kernel_launch(void* const* d_in, const int* in_sizes, int n_in,
                              void* d_out, int out_size) {
    const float* x  = (const float*)d_in[0];
    const float* Wq = (const float*)d_in[1];
    const float* Wk = (const float*)d_in[2];
    const float* Wv = (const float*)d_in[3];
    const float* E  = (const float*)d_in[4];
    const float* F  = (const float*)d_in[5];
    float* out = (float*)d_out;

    combine_w_kernel<<<(192 * 1024) / 256, 256>>>(Wq, Wk, Wv, E, F);

    cudaFuncSetAttribute(proj_mma_kernel, cudaFuncAttributeMaxDynamicSharedMemorySize, PROJ_SMEM_BYTES);
    proj_mma_kernel<<<BT_ / 128, 256, PROJ_SMEM_BYTES>>>(x);

    cudaFuncSetAttribute(attn_mma_kernel, cudaFuncAttributeMaxDynamicSharedMemorySize, ATTN_SMEM_BYTES);
    attn_mma_kernel<<<dim3(16, B_), 256, ATTN_SMEM_BYTES>>>(out);
}

// round 8
// speedup vs baseline: 2.5129x; 1.0616x over previous
#include <cuda_runtime.h>
#include <cuda_bf16.h>
#include <cstdint>

#define B_  8
#define T_  2048
#define C_  1024
#define H_  64
#define BT_  (B_ * T_)          // 16384
#define BTH_ (BT_ * H_)         // 1048576

// ---------------- device scratch (no allocations allowed) ----------------
__device__ __nv_bfloat16 g_W3h[192 * 1024];
__device__ __nv_bfloat16 g_W3l[192 * 1024];
// hi/lo bf16 split of projected Q (pre-scaled), Kp, Vp — [B,T,H] row-major
__device__ __nv_bfloat16 g_qh[BTH_], g_ql[BTH_];
__device__ __nv_bfloat16 g_kh[BTH_], g_kl[BTH_];
__device__ __nv_bfloat16 g_vh[BTH_], g_vl[BTH_];

// ================= helpers =================
__device__ __forceinline__ uint32_t smem_u32(const void* p) {
    uint32_t a;
    asm("{ .reg .u64 t; cvta.to.shared.u64 t, %1; cvt.u32.u64 %0, t; }" : "=r"(a) : "l"(p));
    return a;
}
__device__ __forceinline__ float ex2f(float x) {
    float y;
    asm("ex2.approx.ftz.f32 %0, %1;" : "=f"(y) : "f"(x));
    return y;
}
__device__ __forceinline__ uint32_t pack_bf16(__nv_bfloat16 a, __nv_bfloat16 b) {
    __nv_bfloat162 t(a, b);
    return *reinterpret_cast<uint32_t*>(&t);
}
__device__ __forceinline__ void split2(float v0, float v1, uint32_t& h, uint32_t& l) {
    __nv_bfloat16 h0 = __float2bfloat16(v0), h1 = __float2bfloat16(v1);
    float r0 = v0 - __bfloat162float(h0), r1 = v1 - __bfloat162float(h1);
    h = pack_bf16(h0, h1);
    l = pack_bf16(__float2bfloat16(r0), __float2bfloat16(r1));
}
#define LDSM4(r, addr) \
    asm volatile("ldmatrix.sync.aligned.m8n8.x4.shared.b16 {%0,%1,%2,%3}, [%4];" \
                 : "=r"((r)[0]), "=r"((r)[1]), "=r"((r)[2]), "=r"((r)[3]) : "r"(addr))
#define LDSM4T(r, addr) \
    asm volatile("ldmatrix.sync.aligned.m8n8.x4.trans.shared.b16 {%0,%1,%2,%3}, [%4];" \
                 : "=r"((r)[0]), "=r"((r)[1]), "=r"((r)[2]), "=r"((r)[3]) : "r"(addr))
#define MMA16816(c, a, b0, b1) \
    asm volatile("mma.sync.aligned.m16n8k16.row.col.f32.bf16.bf16.f32 " \
                 "{%0,%1,%2,%3}, {%4,%5,%6,%7}, {%8,%9}, {%0,%1,%2,%3};" \
                 : "+f"((c)[0]), "+f"((c)[1]), "+f"((c)[2]), "+f"((c)[3]) \
                 : "r"((a)[0]), "r"((a)[1]), "r"((a)[2]), "r"((a)[3]), "r"(b0), "r"(b1))
#define CP_ASYNC16(dst, src) \
    asm volatile("cp.async.cg.shared.global [%0], [%1], 16;" :: "r"(dst), "l"(src))
#define CP_COMMIT() asm volatile("cp.async.commit_group;")
#define CP_WAIT(n)  asm volatile("cp.async.wait_group %0;" :: "n"(n))

// ---------------- kernel 1: fuse E/F into K/V weights, emit bf16 hi/lo ----------------
__global__ void combine_w_kernel(const float* __restrict__ Wq, const float* __restrict__ Wk,
                                 const float* __restrict__ Wv, const float* __restrict__ E,
                                 const float* __restrict__ F) {
    int idx = blockIdx.x * 256 + threadIdx.x;     // 192*1024 total
    int n = idx >> 10, c = idx & 1023;
    float val;
    if (n < 64) {
        val = Wq[n * 1024 + c];
    } else if (n < 128) {
        int d = n - 64;
        float s = 0.f;
        #pragma unroll
        for (int h = 0; h < 64; ++h) s += E[h * 64 + d] * Wk[h * 1024 + c];
        val = s;
    } else {
        int d = n - 128;
        float s = 0.f;
        #pragma unroll
        for (int h = 0; h < 64; ++h) s += F[h * 64 + d] * Wv[h * 1024 + c];
        val = s;
    }
    __nv_bfloat16 hi = __float2bfloat16(val);
    __nv_bfloat16 lo = __float2bfloat16(val - __bfloat162float(hi));
    g_W3h[n * 1024 + c] = hi;
    g_W3l[n * 1024 + c] = lo;
}

// ---------------- kernel 2: merged mma.sync projection GEMM ----------------
// CTA: 128(M) x 192(N, all of Q/K/V), BK=32, 8 warps (4m x 2n), 3 n-block loop.
// __launch_bounds__(256, 1): 96 fp32 accums/thread need the full register budget —
// without minBlocks=1 ptxas caps regs and spills the accumulators to local.
#define ASTRIDE 40   // 32 + 8 pad bf16 elems -> 80B rows, conflict-free LDSM
#define PROJ_A_ELEMS (128 * ASTRIDE)
#define PROJ_B_ELEMS (192 * ASTRIDE)
#define PROJ_SMEM_BYTES ((2 * PROJ_A_ELEMS + 2 * PROJ_B_ELEMS) * 2)   // 51200

__global__ __launch_bounds__(256, 1) void proj_mma_kernel(const float* __restrict__ x) {
    extern __shared__ __nv_bfloat16 psm[];
    __nv_bfloat16* Ah = psm;
    __nv_bfloat16* Al = Ah + PROJ_A_ELEMS;
    __nv_bfloat16* Bh = Al + PROJ_A_ELEMS;
    __nv_bfloat16* Bl = Bh + PROJ_B_ELEMS;

    const int tid = threadIdx.x;
    const int lane = tid & 31, w = tid >> 5;
    const int wm = w & 3, wn = w >> 2;
    const int m0 = blockIdx.x * 128;

    float c[3][2][4][4];
    #pragma unroll
    for (int n = 0; n < 3; ++n)
        #pragma unroll
        for (int i = 0; i < 2; ++i)
            #pragma unroll
            for (int j = 0; j < 4; ++j)
                #pragma unroll
                for (int q = 0; q < 4; ++q) c[n][i][j][q] = 0.f;

    const int arow = wm * 32 + (lane & 15);
    const int brow = wn * 32 + (lane & 15);
    const int koff = (lane >> 4) * 8;

    for (int kt = 0; kt < 1024; kt += 32) {
        __syncthreads();
        // A tile: 128x32 fp32 -> bf16 hi/lo (converted once, reused by all 3 n-blocks)
        #pragma unroll
        for (int u = 0; u < 4; ++u) {
            int idx = tid + u * 256;
            int row = idx >> 3, c4 = (idx & 7) * 4;
            float4 v = *(const float4*)(x + (size_t)(m0 + row) * 1024 + kt + c4);
            __nv_bfloat16 h0 = __float2bfloat16(v.x), h1 = __float2bfloat16(v.y);
            __nv_bfloat16 h2 = __float2bfloat16(v.z), h3 = __float2bfloat16(v.w);
            __nv_bfloat16 l0 = __float2bfloat16(v.x - __bfloat162float(h0));
            __nv_bfloat16 l1 = __float2bfloat16(v.y - __bfloat162float(h1));
            __nv_bfloat16 l2 = __float2bfloat16(v.z - __bfloat162float(h2));
            __nv_bfloat16 l3 = __float2bfloat16(v.w - __bfloat162float(h3));
            *(uint2*)&Ah[row * ASTRIDE + c4] = make_uint2(pack_bf16(h0, h1), pack_bf16(h2, h3));
            *(uint2*)&Al[row * ASTRIDE + c4] = make_uint2(pack_bf16(l0, l1), pack_bf16(l2, l3));
        }
        // B tile: all 192 weight rows x 32, hi/lo. 768 uint4 each, 3/thread.
        #pragma unroll
        for (int u = 0; u < 3; ++u) {
            int idx = tid + u * 256;
            int row = idx >> 2, c8 = (idx & 3) * 8;
            size_t g = (size_t)row * 1024 + kt + c8;
            *(uint4*)&Bh[row * ASTRIDE + c8] = *(const uint4*)(g_W3h + g);
            *(uint4*)&Bl[row * ASTRIDE + c8] = *(const uint4*)(g_W3l + g);
        }
        __syncthreads();

        #pragma unroll
        for (int p = 0; p < 3; ++p) {
            const __nv_bfloat16* As = (p == 1) ? Al : Ah;
            const __nv_bfloat16* Bs = (p == 2) ? Bl : Bh;
            #pragma unroll
            for (int k16 = 0; k16 < 2; ++k16) {
                uint32_t a[2][4];
                #pragma unroll
                for (int s = 0; s < 2; ++s)
                    LDSM4(a[s], smem_u32(&As[(arow + s * 16) * ASTRIDE + k16 * 16 + koff]));
                #pragma unroll
                for (int nblk = 0; nblk < 3; ++nblk) {
                    uint32_t b[2][4];
                    #pragma unroll
                    for (int s = 0; s < 2; ++s)
                        LDSM4(b[s], smem_u32(&Bs[(nblk * 64 + brow + s * 16) * ASTRIDE + k16 * 16 + koff]));
                    #pragma unroll
                    for (int ms = 0; ms < 2; ++ms)
                        #pragma unroll
                        for (int nb = 0; nb < 4; ++nb)
                            MMA16816(c[nblk][ms][nb], a[ms], b[nb >> 1][nb & 1], b[nb >> 1][(nb & 1) + 2]);
                }
            }
        }
    }

    // epilogue: hi/lo bf16 split straight to the attention operand tensors
    #pragma unroll
    for (int nblk = 0; nblk < 3; ++nblk) {
        const float scale = (nblk == 0) ? (0.0625f * 1.4426950408889634f) : 1.0f;
        __nv_bfloat16* ph = (nblk == 0) ? g_qh : (nblk == 1 ? g_kh : g_vh);
        __nv_bfloat16* pl = (nblk == 0) ? g_ql : (nblk == 1 ? g_kl : g_vl);
        #pragma unroll
        for (int ms = 0; ms < 2; ++ms) {
            int r0 = m0 + wm * 32 + ms * 16 + (lane >> 2);
            #pragma unroll
            for (int nb = 0; nb < 4; ++nb) {
                int col = wn * 32 + nb * 8 + (lane & 3) * 2;
                uint32_t h, l;
                split2(c[nblk][ms][nb][0] * scale, c[nblk][ms][nb][1] * scale, h, l);
                *(uint32_t*)&ph[(size_t)r0 * 64 + col] = h;
                *(uint32_t*)&pl[(size_t)r0 * 64 + col] = l;
                split2(c[nblk][ms][nb][2] * scale, c[nblk][ms][nb][3] * scale, h, l);
                *(uint32_t*)&ph[(size_t)(r0 + 8) * 64 + col] = h;
                *(uint32_t*)&pl[(size_t)(r0 + 8) * 64 + col] = l;
            }
        }
    }
}

// ---------------- kernel 3: tensor-core causal flash attention ----------------
// CTA: 128 q-rows x 128-key tiles, 8 warps (16 rows each).
// __launch_bounds__(256, 1): s[16][4]+o[8][4] = 96 accum floats/thread — same
// spill hazard as proj; minBlocks=1 lifts the ptxas register cap (1 CTA/SM
// anyway due to 184KB smem).
#define QSTRIDE 72
#define TEN_ELEMS (128 * QSTRIDE)                 // one 128x64(+pad) bf16 tensor
#define STAGE_ELEMS (4 * TEN_ELEMS)               // Kh,Kl,Vh,Vl
#define ATTN_SMEM_BYTES ((2 * TEN_ELEMS + 2 * STAGE_ELEMS) * 2)   // 184320

__global__ __launch_bounds__(256, 1) void attn_mma_kernel(float* __restrict__ out) {
    extern __shared__ __nv_bfloat16 sb[];
    __nv_bfloat16* Qh = sb;
    __nv_bfloat16* Ql = sb + TEN_ELEMS;
    __nv_bfloat16* Stg = sb + 2 * TEN_ELEMS;      // [2][4][TEN_ELEMS]

    const int b = blockIdx.y;
    const int qt = 15 - blockIdx.x;               // LPT: biggest q-tiles first
    const int tid = threadIdx.x;
    const int lane = tid & 31, w = tid >> 5;
    const int rowg0 = qt * 128;
    const size_t qbase = ((size_t)(b * T_) + rowg0) * H_;
    const size_t kvbase = (size_t)(b * T_) * H_;

    // load Q tile (128x64 hi/lo) — plain loads, covered by first syncthreads
    #pragma unroll
    for (int u = 0; u < 4; ++u) {
        int idx = tid + u * 256;
        int row = idx >> 3, c8 = (idx & 7) * 8;
        *(uint4*)&Qh[row * QSTRIDE + c8] = *(const uint4*)(g_qh + qbase + (size_t)row * 64 + c8);
        *(uint4*)&Ql[row * QSTRIDE + c8] = *(const uint4*)(g_ql + qbase + (size_t)row * 64 + c8);
    }

    const __nv_bfloat16* gsrc[4] = {g_kh, g_kl, g_vh, g_vl};

    // prefetch helper: 4 tensors x 1024 uint4, 16 cp.async per thread
    auto prefetch = [&](int stg, int kt) {
        __nv_bfloat16* dst = Stg + stg * STAGE_ELEMS;
        size_t base = kvbase + (size_t)kt * 128 * 64;
        #pragma unroll
        for (int t = 0; t < 4; ++t) {
            #pragma unroll
            for (int u = 0; u < 4; ++u) {
                int idx = tid + u * 256;
                int row = idx >> 3, c8 = (idx & 7) * 8;
                CP_ASYNC16(smem_u32(&dst[t * TEN_ELEMS + row * QSTRIDE + c8]),
                           gsrc[t] + base + (size_t)row * 64 + c8);
            }
        }
    };

    prefetch(0, 0);
    CP_COMMIT();

    float m0 = -1e30f, m1 = -1e30f, l0 = 0.f, l1 = 0.f;
    float o[8][4];
    #pragma unroll
    for (int i = 0; i < 8; ++i)
        #pragma unroll
        for (int q = 0; q < 4; ++q) o[i][q] = 0.f;

    const int arow = w * 16 + (lane & 15);
    const int koff = (lane >> 4) * 8;
    const int r0loc = lane >> 2;

    const int ntiles = qt + 1;
    for (int kt = 0; kt < ntiles; ++kt) {
        // issue next prefetch into the stage freed at end of iter kt-1
        if (kt + 1 < ntiles) {
            prefetch((kt + 1) & 1, kt + 1);
            CP_COMMIT();
            CP_WAIT(1);                 // wait for stage kt's group
        } else {
            CP_WAIT(0);
        }
        __syncthreads();

        const __nv_bfloat16* Kh = Stg + (kt & 1) * STAGE_ELEMS;
        const __nv_bfloat16* Kl = Kh + TEN_ELEMS;
        const __nv_bfloat16* Vh = Kh + 2 * TEN_ELEMS;
        const __nv_bfloat16* Vl = Kh + 3 * TEN_ELEMS;

        // ---- S = Q @ K^T (hh + lh + hl) ----
        float s[16][4];
        #pragma unroll
        for (int nb = 0; nb < 16; ++nb)
            #pragma unroll
            for (int q = 0; q < 4; ++q) s[nb][q] = 0.f;

        #pragma unroll
        for (int k16 = 0; k16 < 4; ++k16) {
            uint32_t ah[4], al[4];
            LDSM4(ah, smem_u32(&Qh[arow * QSTRIDE + k16 * 16 + koff]));
            LDSM4(al, smem_u32(&Ql[arow * QSTRIDE + k16 * 16 + koff]));
            #pragma unroll
            for (int g = 0; g < 8; ++g) {
                uint32_t bh[4], bl[4];
                LDSM4(bh, smem_u32(&Kh[(g * 16 + (lane & 15)) * QSTRIDE + k16 * 16 + koff]));
                LDSM4(bl, smem_u32(&Kl[(g * 16 + (lane & 15)) * QSTRIDE + k16 * 16 + koff]));
                MMA16816(s[2 * g],     ah, bh[0], bh[2]);
                MMA16816(s[2 * g],     al, bh[0], bh[2]);
                MMA16816(s[2 * g],     ah, bl[0], bl[2]);
                MMA16816(s[2 * g + 1], ah, bh[1], bh[3]);
                MMA16816(s[2 * g + 1], al, bh[1], bh[3]);
                MMA16816(s[2 * g + 1], ah, bl[1], bl[3]);
            }
        }

        // ---- causal mask (diagonal tile only) ----
        if (kt == ntiles - 1) {
            int ig0 = rowg0 + w * 16 + r0loc;
            #pragma unroll
            for (int nb = 0; nb < 16; ++nb) {
                int cg = kt * 128 + nb * 8 + (lane & 3) * 2;
                if (cg > ig0)         s[nb][0] = -1e30f;
                if (cg + 1 > ig0)     s[nb][1] = -1e30f;
                if (cg > ig0 + 8)     s[nb][2] = -1e30f;
                if (cg + 1 > ig0 + 8) s[nb][3] = -1e30f;
            }
        }

        // ---- online softmax (base-2) ----
        float mx0 = -1e30f, mx1 = -1e30f;
        #pragma unroll
        for (int nb = 0; nb < 16; ++nb) {
            mx0 = fmaxf(mx0, fmaxf(s[nb][0], s[nb][1]));
            mx1 = fmaxf(mx1, fmaxf(s[nb][2], s[nb][3]));
        }
        mx0 = fmaxf(mx0, __shfl_xor_sync(0xffffffffu, mx0, 1));
        mx0 = fmaxf(mx0, __shfl_xor_sync(0xffffffffu, mx0, 2));
        mx1 = fmaxf(mx1, __shfl_xor_sync(0xffffffffu, mx1, 1));
        mx1 = fmaxf(mx1, __shfl_xor_sync(0xffffffffu, mx1, 2));
        float mn0 = fmaxf(m0, mx0), mn1 = fmaxf(m1, mx1);
        float al0 = ex2f(m0 - mn0), al1 = ex2f(m1 - mn1);
        m0 = mn0; m1 = mn1;
        #pragma unroll
        for (int i = 0; i < 8; ++i) {
            o[i][0] *= al0; o[i][1] *= al0;
            o[i][2] *= al1; o[i][3] *= al1;
        }
        float rs0 = 0.f, rs1 = 0.f;
        #pragma unroll
        for (int nb = 0; nb < 16; ++nb) {
            float p0 = ex2f(s[nb][0] - mn0); s[nb][0] = p0; rs0 += p0;
            float p1 = ex2f(s[nb][1] - mn0); s[nb][1] = p1; rs0 += p1;
            float p2 = ex2f(s[nb][2] - mn1); s[nb][2] = p2; rs1 += p2;
            float p3 = ex2f(s[nb][3] - mn1); s[nb][3] = p3; rs1 += p3;
        }
        rs0 += __shfl_xor_sync(0xffffffffu, rs0, 1);
        rs0 += __shfl_xor_sync(0xffffffffu, rs0, 2);
        rs1 += __shfl_xor_sync(0xffffffffu, rs1, 1);
        rs1 += __shfl_xor_sync(0xffffffffu, rs1, 2);
        l0 = l0 * al0 + rs0;
        l1 = l1 * al1 + rs1;

        // ---- O += P @ V (P register-resident, V via ldmatrix.trans) ----
        #pragma unroll
        for (int kb = 0; kb < 8; ++kb) {
            uint32_t ph[4], pl[4];
            split2(s[2 * kb][0],     s[2 * kb][1],     ph[0], pl[0]);
            split2(s[2 * kb][2],     s[2 * kb][3],     ph[1], pl[1]);
            split2(s[2 * kb + 1][0], s[2 * kb + 1][1], ph[2], pl[2]);
            split2(s[2 * kb + 1][2], s[2 * kb + 1][3], ph[3], pl[3]);
            #pragma unroll
            for (int g = 0; g < 4; ++g) {
                uint32_t bh[4], bl[4];
                LDSM4T(bh, smem_u32(&Vh[(kb * 16 + (lane & 15)) * QSTRIDE + g * 16 + koff]));
                LDSM4T(bl, smem_u32(&Vl[(kb * 16 + (lane & 15)) * QSTRIDE + g * 16 + koff]));
                MMA16816(o[2 * g],     ph, bh[0], bh[1]);
                MMA16816(o[2 * g],     pl, bh[0], bh[1]);
                MMA16816(o[2 * g],     ph, bl[0], bl[1]);
                MMA16816(o[2 * g + 1], ph, bh[2], bh[3]);
                MMA16816(o[2 * g + 1], pl, bh[2], bh[3]);
                MMA16816(o[2 * g + 1], ph, bl[2], bl[3]);
            }
        }
        __syncthreads();   // everyone done reading this stage before it is overwritten
    }

    // ---- epilogue: normalize and store ----
    float inv0 = 1.0f / l0, inv1 = 1.0f / l1;
    int rg = rowg0 + w * 16 + r0loc;
    float* op0 = out + ((size_t)(b * T_) + rg) * 64;
    float* op1 = op0 + 8 * 64;
    int col0 = (lane & 3) * 2;
    #pragma unroll
    for (int nbo = 0; nbo < 8; ++nbo) {
        int col = nbo * 8 + col0;
        *(float2*)(op0 + col) = make_float2(o[nbo][0] * inv0, o[nbo][1] * inv0);
        *(float2*)(op1 + col) = make_float2(o[nbo][2] * inv1, o[nbo][3] * inv1);
    }
}

// ---------------- launch ----------------
extern "C" void kernel_launch(void* const* d_in, const int* in_sizes, int n_in,
                              void* d_out, int out_size) {
    const float* x  = (const float*)d_in[0];
    const float* Wq = (const float*)d_in[1];
    const float* Wk = (const float*)d_in[2];
    const float* Wv = (const float*)d_in[3];
    const float* E  = (const float*)d_in[4];
    const float* F  = (const float*)d_in[5];
    float* out = (float*)d_out;

    combine_w_kernel<<<(192 * 1024) / 256, 256>>>(Wq, Wk, Wv, E, F);

    cudaFuncSetAttribute(proj_mma_kernel, cudaFuncAttributeMaxDynamicSharedMemorySize, PROJ_SMEM_BYTES);
    proj_mma_kernel<<<BT_ / 128, 256, PROJ_SMEM_BYTES>>>(x);

    cudaFuncSetAttribute(attn_mma_kernel, cudaFuncAttributeMaxDynamicSharedMemorySize, ATTN_SMEM_BYTES);
    attn_mma_kernel<<<dim3(16, B_), 256, ATTN_SMEM_BYTES>>>(out);
}

// round 9
// speedup vs baseline: 2.9391x; 1.1696x over previous
#include <cuda_runtime.h>
#include <cuda_bf16.h>
#include <cstdint>

#define B_  8
#define T_  2048
#define C_  1024
#define H_  64
#define BT_  (B_ * T_)          // 16384
#define BTH_ (BT_ * H_)         // 1048576

// ---------------- device scratch (no allocations allowed) ----------------
__device__ __nv_bfloat16 g_W3h[192 * 1024];
__device__ __nv_bfloat16 g_W3l[192 * 1024];
// hi/lo bf16 split of projected Q (pre-scaled), Kp, Vp — [B,T,H] row-major
__device__ __nv_bfloat16 g_qh[BTH_], g_ql[BTH_];
__device__ __nv_bfloat16 g_kh[BTH_], g_kl[BTH_];
__device__ __nv_bfloat16 g_vh[BTH_], g_vl[BTH_];

// ================= helpers =================
__device__ __forceinline__ uint32_t smem_u32(const void* p) {
    uint32_t a;
    asm("{ .reg .u64 t; cvta.to.shared.u64 t, %1; cvt.u32.u64 %0, t; }" : "=r"(a) : "l"(p));
    return a;
}
__device__ __forceinline__ float ex2f(float x) {
    float y;
    asm("ex2.approx.ftz.f32 %0, %1;" : "=f"(y) : "f"(x));
    return y;
}
__device__ __forceinline__ uint32_t pack_bf16(__nv_bfloat16 a, __nv_bfloat16 b) {
    __nv_bfloat162 t(a, b);
    return *reinterpret_cast<uint32_t*>(&t);
}
__device__ __forceinline__ void split2(float v0, float v1, uint32_t& h, uint32_t& l) {
    __nv_bfloat16 h0 = __float2bfloat16(v0), h1 = __float2bfloat16(v1);
    float r0 = v0 - __bfloat162float(h0), r1 = v1 - __bfloat162float(h1);
    h = pack_bf16(h0, h1);
    l = pack_bf16(__float2bfloat16(r0), __float2bfloat16(r1));
}
#define LDSM4(r, addr) \
    asm volatile("ldmatrix.sync.aligned.m8n8.x4.shared.b16 {%0,%1,%2,%3}, [%4];" \
                 : "=r"((r)[0]), "=r"((r)[1]), "=r"((r)[2]), "=r"((r)[3]) : "r"(addr))
#define LDSM4T(r, addr) \
    asm volatile("ldmatrix.sync.aligned.m8n8.x4.trans.shared.b16 {%0,%1,%2,%3}, [%4];" \
                 : "=r"((r)[0]), "=r"((r)[1]), "=r"((r)[2]), "=r"((r)[3]) : "r"(addr))
#define MMA16816(c, a, b0, b1) \
    asm volatile("mma.sync.aligned.m16n8k16.row.col.f32.bf16.bf16.f32 " \
                 "{%0,%1,%2,%3}, {%4,%5,%6,%7}, {%8,%9}, {%0,%1,%2,%3};" \
                 : "+f"((c)[0]), "+f"((c)[1]), "+f"((c)[2]), "+f"((c)[3]) \
                 : "r"((a)[0]), "r"((a)[1]), "r"((a)[2]), "r"((a)[3]), "r"(b0), "r"(b1))
#define CP_ASYNC16(dst, src) \
    asm volatile("cp.async.cg.shared.global [%0], [%1], 16;" :: "r"(dst), "l"(src))
#define CP_COMMIT() asm volatile("cp.async.commit_group;")
#define CP_WAIT(n)  asm volatile("cp.async.wait_group %0;" :: "n"(n))

// ---------------- kernel 1: fuse E/F into K/V weights, emit bf16 hi/lo ----------------
__global__ void combine_w_kernel(const float* __restrict__ Wq, const float* __restrict__ Wk,
                                 const float* __restrict__ Wv, const float* __restrict__ E,
                                 const float* __restrict__ F) {
    int idx = blockIdx.x * 256 + threadIdx.x;     // 192*1024 total
    int n = idx >> 10, c = idx & 1023;
    float val;
    if (n < 64) {
        val = Wq[n * 1024 + c];
    } else if (n < 128) {
        int d = n - 64;
        float s = 0.f;
        #pragma unroll
        for (int h = 0; h < 64; ++h) s += E[h * 64 + d] * Wk[h * 1024 + c];
        val = s;
    } else {
        int d = n - 128;
        float s = 0.f;
        #pragma unroll
        for (int h = 0; h < 64; ++h) s += F[h * 64 + d] * Wv[h * 1024 + c];
        val = s;
    }
    __nv_bfloat16 hi = __float2bfloat16(val);
    __nv_bfloat16 lo = __float2bfloat16(val - __bfloat162float(hi));
    g_W3h[n * 1024 + c] = hi;
    g_W3l[n * 1024 + c] = lo;
}

// ---------------- kernel 2: merged mma.sync projection GEMM (unchanged) ----------------
#define ASTRIDE 40
#define PROJ_A_ELEMS (128 * ASTRIDE)
#define PROJ_B_ELEMS (192 * ASTRIDE)
#define PROJ_SMEM_BYTES ((2 * PROJ_A_ELEMS + 2 * PROJ_B_ELEMS) * 2)   // 51200

__global__ __launch_bounds__(256, 1) void proj_mma_kernel(const float* __restrict__ x) {
    extern __shared__ __nv_bfloat16 psm[];
    __nv_bfloat16* Ah = psm;
    __nv_bfloat16* Al = Ah + PROJ_A_ELEMS;
    __nv_bfloat16* Bh = Al + PROJ_A_ELEMS;
    __nv_bfloat16* Bl = Bh + PROJ_B_ELEMS;

    const int tid = threadIdx.x;
    const int lane = tid & 31, w = tid >> 5;
    const int wm = w & 3, wn = w >> 2;
    const int m0 = blockIdx.x * 128;

    float c[3][2][4][4];
    #pragma unroll
    for (int n = 0; n < 3; ++n)
        #pragma unroll
        for (int i = 0; i < 2; ++i)
            #pragma unroll
            for (int j = 0; j < 4; ++j)
                #pragma unroll
                for (int q = 0; q < 4; ++q) c[n][i][j][q] = 0.f;

    const int arow = wm * 32 + (lane & 15);
    const int brow = wn * 32 + (lane & 15);
    const int koff = (lane >> 4) * 8;

    for (int kt = 0; kt < 1024; kt += 32) {
        __syncthreads();
        #pragma unroll
        for (int u = 0; u < 4; ++u) {
            int idx = tid + u * 256;
            int row = idx >> 3, c4 = (idx & 7) * 4;
            float4 v = *(const float4*)(x + (size_t)(m0 + row) * 1024 + kt + c4);
            __nv_bfloat16 h0 = __float2bfloat16(v.x), h1 = __float2bfloat16(v.y);
            __nv_bfloat16 h2 = __float2bfloat16(v.z), h3 = __float2bfloat16(v.w);
            __nv_bfloat16 l0 = __float2bfloat16(v.x - __bfloat162float(h0));
            __nv_bfloat16 l1 = __float2bfloat16(v.y - __bfloat162float(h1));
            __nv_bfloat16 l2 = __float2bfloat16(v.z - __bfloat162float(h2));
            __nv_bfloat16 l3 = __float2bfloat16(v.w - __bfloat162float(h3));
            *(uint2*)&Ah[row * ASTRIDE + c4] = make_uint2(pack_bf16(h0, h1), pack_bf16(h2, h3));
            *(uint2*)&Al[row * ASTRIDE + c4] = make_uint2(pack_bf16(l0, l1), pack_bf16(l2, l3));
        }
        #pragma unroll
        for (int u = 0; u < 3; ++u) {
            int idx = tid + u * 256;
            int row = idx >> 2, c8 = (idx & 3) * 8;
            size_t g = (size_t)row * 1024 + kt + c8;
            *(uint4*)&Bh[row * ASTRIDE + c8] = *(const uint4*)(g_W3h + g);
            *(uint4*)&Bl[row * ASTRIDE + c8] = *(const uint4*)(g_W3l + g);
        }
        __syncthreads();

        #pragma unroll
        for (int p = 0; p < 3; ++p) {
            const __nv_bfloat16* As = (p == 1) ? Al : Ah;
            const __nv_bfloat16* Bs = (p == 2) ? Bl : Bh;
            #pragma unroll
            for (int k16 = 0; k16 < 2; ++k16) {
                uint32_t a[2][4];
                #pragma unroll
                for (int s = 0; s < 2; ++s)
                    LDSM4(a[s], smem_u32(&As[(arow + s * 16) * ASTRIDE + k16 * 16 + koff]));
                #pragma unroll
                for (int nblk = 0; nblk < 3; ++nblk) {
                    uint32_t b[2][4];
                    #pragma unroll
                    for (int s = 0; s < 2; ++s)
                        LDSM4(b[s], smem_u32(&Bs[(nblk * 64 + brow + s * 16) * ASTRIDE + k16 * 16 + koff]));
                    #pragma unroll
                    for (int ms = 0; ms < 2; ++ms)
                        #pragma unroll
                        for (int nb = 0; nb < 4; ++nb)
                            MMA16816(c[nblk][ms][nb], a[ms], b[nb >> 1][nb & 1], b[nb >> 1][(nb & 1) + 2]);
                }
            }
        }
    }

    #pragma unroll
    for (int nblk = 0; nblk < 3; ++nblk) {
        const float scale = (nblk == 0) ? (0.0625f * 1.4426950408889634f) : 1.0f;
        __nv_bfloat16* ph = (nblk == 0) ? g_qh : (nblk == 1 ? g_kh : g_vh);
        __nv_bfloat16* pl = (nblk == 0) ? g_ql : (nblk == 1 ? g_kl : g_vl);
        #pragma unroll
        for (int ms = 0; ms < 2; ++ms) {
            int r0 = m0 + wm * 32 + ms * 16 + (lane >> 2);
            #pragma unroll
            for (int nb = 0; nb < 4; ++nb) {
                int col = wn * 32 + nb * 8 + (lane & 3) * 2;
                uint32_t h, l;
                split2(c[nblk][ms][nb][0] * scale, c[nblk][ms][nb][1] * scale, h, l);
                *(uint32_t*)&ph[(size_t)r0 * 64 + col] = h;
                *(uint32_t*)&pl[(size_t)r0 * 64 + col] = l;
                split2(c[nblk][ms][nb][2] * scale, c[nblk][ms][nb][3] * scale, h, l);
                *(uint32_t*)&ph[(size_t)(r0 + 8) * 64 + col] = h;
                *(uint32_t*)&pl[(size_t)(r0 + 8) * 64 + col] = l;
            }
        }
    }
}

// ---------------- kernel 3: balanced tensor-core causal flash attention ----------------
// Each CTA = antithetical 64-row q-tile pair (p, 31-p): EXACTLY 17 key-iters per
// CTA -> perfect load balance (was 53% util). 8 warps = 4 row-groups x 2 key
// halves; one smem max-exchange per iter; O/l merged per phase in the epilogue.
#define QSTRIDE 72
#define TEN_ELEMS (128 * QSTRIDE)
#define STAGE_ELEMS (4 * TEN_ELEMS)
#define BF16_ELEMS (2 * TEN_ELEMS + 2 * STAGE_ELEMS)
#define ORED_STRIDE 66
#define ATTN_SMEM_BYTES (BF16_ELEMS * 2 + 64 * ORED_STRIDE * 4 + 2 * 64 * 4)   // 201728

__global__ __launch_bounds__(256, 1) void attn_mma_kernel(float* __restrict__ out) {
    extern __shared__ __nv_bfloat16 sb[];
    __nv_bfloat16* Qh = sb;
    __nv_bfloat16* Ql = sb + TEN_ELEMS;
    __nv_bfloat16* Stg = sb + 2 * TEN_ELEMS;          // [2][4][TEN_ELEMS]
    float* Ored = (float*)(sb + BF16_ELEMS);          // [64][ORED_STRIDE]
    float* red  = Ored + 64 * ORED_STRIDE;            // [2][64] (max per iter; l at epilogue)

    const int b = blockIdx.y;
    const int p = blockIdx.x;                          // pair index 0..15
    const int tid = threadIdx.x;
    const int lane = tid & 31, w = tid >> 5;
    const int wr = w & 3;                              // row group (16 rows)
    const int wc = w >> 2;                             // key half (0/1)
    const size_t kvbase = (size_t)(b * T_) * H_;
    const int qts[2] = {p, 31 - p};

    // load Q for both tiles: smem rows 0-63 = tile A, 64-127 = tile B
    #pragma unroll
    for (int u = 0; u < 4; ++u) {
        int idx = tid + u * 256;
        int row = idx >> 3, c8 = (idx & 7) * 8;
        size_t g = ((size_t)(b * T_) + qts[row >> 6] * 64 + (row & 63)) * H_ + c8;
        *(uint4*)&Qh[row * QSTRIDE + c8] = *(const uint4*)(g_qh + g);
        *(uint4*)&Ql[row * QSTRIDE + c8] = *(const uint4*)(g_ql + g);
    }

    const __nv_bfloat16* gsrc[4] = {g_kh, g_kl, g_vh, g_vl};
    auto prefetch = [&](int stg, int kt) {
        __nv_bfloat16* dst = Stg + stg * STAGE_ELEMS;
        size_t base = kvbase + (size_t)kt * 128 * 64;
        #pragma unroll
        for (int t = 0; t < 4; ++t) {
            #pragma unroll
            for (int u = 0; u < 4; ++u) {
                int idx = tid + u * 256;
                int row = idx >> 3, c8 = (idx & 7) * 8;
                CP_ASYNC16(smem_u32(&dst[t * TEN_ELEMS + row * QSTRIDE + c8]),
                           gsrc[t] + base + (size_t)row * 64 + c8);
            }
        }
    };

    prefetch(0, 0);
    CP_COMMIT();

    int sidx = 0;
    const int koff = (lane >> 4) * 8;
    const int r0loc = lane >> 2;
    const int rg = wr * 16 + r0loc;                    // row within 64-row tile

    #pragma unroll 1
    for (int phase = 0; phase < 2; ++phase) {
        const int qt = qts[phase];
        const int rowg0 = qt * 64;
        const int ntiles = (qt >> 1) + 1;
        const int arow = phase * 64 + wr * 16 + (lane & 15);

        float m0 = -1e30f, m1 = -1e30f, l0 = 0.f, l1 = 0.f;
        float o[8][4];
        #pragma unroll
        for (int i = 0; i < 8; ++i)
            #pragma unroll
            for (int q = 0; q < 4; ++q) o[i][q] = 0.f;

        for (int kt = 0; kt < ntiles; ++kt) {
            if (kt + 1 < ntiles) {
                prefetch(sidx ^ 1, kt + 1);  CP_COMMIT();  CP_WAIT(1);
            } else if (phase == 0) {
                prefetch(sidx ^ 1, 0);       CP_COMMIT();  CP_WAIT(1);   // phase B tile 0
            } else {
                CP_WAIT(0);
            }
            __syncthreads();

            const __nv_bfloat16* Kh = Stg + sidx * STAGE_ELEMS;
            const __nv_bfloat16* Kl = Kh + TEN_ELEMS;
            const __nv_bfloat16* Vh = Kh + 2 * TEN_ELEMS;
            const __nv_bfloat16* Vl = Kh + 3 * TEN_ELEMS;

            // ---- S = Q @ K^T over this warp's 64-key half (hh + lh + hl) ----
            float s[8][4];
            #pragma unroll
            for (int nb = 0; nb < 8; ++nb)
                #pragma unroll
                for (int q = 0; q < 4; ++q) s[nb][q] = 0.f;

            #pragma unroll
            for (int k16 = 0; k16 < 4; ++k16) {
                uint32_t ah[4], al[4];
                LDSM4(ah, smem_u32(&Qh[arow * QSTRIDE + k16 * 16 + koff]));
                LDSM4(al, smem_u32(&Ql[arow * QSTRIDE + k16 * 16 + koff]));
                #pragma unroll
                for (int g = 0; g < 4; ++g) {
                    uint32_t bh[4], bl[4];
                    int krow = wc * 64 + g * 16 + (lane & 15);
                    LDSM4(bh, smem_u32(&Kh[krow * QSTRIDE + k16 * 16 + koff]));
                    LDSM4(bl, smem_u32(&Kl[krow * QSTRIDE + k16 * 16 + koff]));
                    MMA16816(s[2 * g],     ah, bh[0], bh[2]);
                    MMA16816(s[2 * g],     al, bh[0], bh[2]);
                    MMA16816(s[2 * g],     ah, bl[0], bl[2]);
                    MMA16816(s[2 * g + 1], ah, bh[1], bh[3]);
                    MMA16816(s[2 * g + 1], al, bh[1], bh[3]);
                    MMA16816(s[2 * g + 1], ah, bl[1], bl[3]);
                }
            }

            // ---- causal mask (diagonal iter only) ----
            if (kt == ntiles - 1) {
                int ig0 = rowg0 + rg;
                #pragma unroll
                for (int nb = 0; nb < 8; ++nb) {
                    int cg = kt * 128 + wc * 64 + nb * 8 + (lane & 3) * 2;
                    if (cg > ig0)         s[nb][0] = -1e30f;
                    if (cg + 1 > ig0)     s[nb][1] = -1e30f;
                    if (cg > ig0 + 8)     s[nb][2] = -1e30f;
                    if (cg + 1 > ig0 + 8) s[nb][3] = -1e30f;
                }
            }

            // ---- online softmax: local quad max, cross-half exchange via smem ----
            float mx0 = -1e30f, mx1 = -1e30f;
            #pragma unroll
            for (int nb = 0; nb < 8; ++nb) {
                mx0 = fmaxf(mx0, fmaxf(s[nb][0], s[nb][1]));
                mx1 = fmaxf(mx1, fmaxf(s[nb][2], s[nb][3]));
            }
            mx0 = fmaxf(mx0, __shfl_xor_sync(0xffffffffu, mx0, 1));
            mx0 = fmaxf(mx0, __shfl_xor_sync(0xffffffffu, mx0, 2));
            mx1 = fmaxf(mx1, __shfl_xor_sync(0xffffffffu, mx1, 1));
            mx1 = fmaxf(mx1, __shfl_xor_sync(0xffffffffu, mx1, 2));
            if ((lane & 3) == 0) {
                red[wc * 64 + rg]     = mx0;
                red[wc * 64 + rg + 8] = mx1;
            }
            __syncthreads();
            mx0 = fmaxf(mx0, red[(wc ^ 1) * 64 + rg]);
            mx1 = fmaxf(mx1, red[(wc ^ 1) * 64 + rg + 8]);

            float mn0 = fmaxf(m0, mx0), mn1 = fmaxf(m1, mx1);
            float al0 = ex2f(m0 - mn0), al1 = ex2f(m1 - mn1);
            m0 = mn0; m1 = mn1;
            #pragma unroll
            for (int i = 0; i < 8; ++i) {
                o[i][0] *= al0; o[i][1] *= al0;
                o[i][2] *= al1; o[i][3] *= al1;
            }
            float rs0 = 0.f, rs1 = 0.f;
            #pragma unroll
            for (int nb = 0; nb < 8; ++nb) {
                float p0 = ex2f(s[nb][0] - mn0); s[nb][0] = p0; rs0 += p0;
                float p1 = ex2f(s[nb][1] - mn0); s[nb][1] = p1; rs0 += p1;
                float p2 = ex2f(s[nb][2] - mn1); s[nb][2] = p2; rs1 += p2;
                float p3 = ex2f(s[nb][3] - mn1); s[nb][3] = p3; rs1 += p3;
            }
            rs0 += __shfl_xor_sync(0xffffffffu, rs0, 1);
            rs0 += __shfl_xor_sync(0xffffffffu, rs0, 2);
            rs1 += __shfl_xor_sync(0xffffffffu, rs1, 1);
            rs1 += __shfl_xor_sync(0xffffffffu, rs1, 2);
            l0 = l0 * al0 + rs0;       // per-warp PARTIAL l (own key half)
            l1 = l1 * al1 + rs1;

            // ---- O += P @ V over this warp's 64-key half ----
            #pragma unroll
            for (int kb = 0; kb < 4; ++kb) {
                uint32_t ph[4], pl[4];
                split2(s[2 * kb][0],     s[2 * kb][1],     ph[0], pl[0]);
                split2(s[2 * kb][2],     s[2 * kb][3],     ph[1], pl[1]);
                split2(s[2 * kb + 1][0], s[2 * kb + 1][1], ph[2], pl[2]);
                split2(s[2 * kb + 1][2], s[2 * kb + 1][3], ph[3], pl[3]);
                #pragma unroll
                for (int g = 0; g < 4; ++g) {
                    uint32_t bh[4], bl[4];
                    int vrow = wc * 64 + kb * 16 + (lane & 15);
                    LDSM4T(bh, smem_u32(&Vh[vrow * QSTRIDE + g * 16 + koff]));
                    LDSM4T(bl, smem_u32(&Vl[vrow * QSTRIDE + g * 16 + koff]));
                    MMA16816(o[2 * g],     ph, bh[0], bh[1]);
                    MMA16816(o[2 * g],     pl, bh[0], bh[1]);
                    MMA16816(o[2 * g],     ph, bl[0], bl[1]);
                    MMA16816(o[2 * g + 1], ph, bh[2], bh[3]);
                    MMA16816(o[2 * g + 1], pl, bh[2], bh[3]);
                    MMA16816(o[2 * g + 1], ph, bl[2], bl[3]);
                }
            }
            sidx ^= 1;
            __syncthreads();    // stage reuse + red reuse
        }

        // ---- phase epilogue: merge key-half partials (O, l), normalize, store ----
        if ((lane & 3) == 0) {
            red[wc * 64 + rg]     = l0;
            red[wc * 64 + rg + 8] = l1;
        }
        if (wc == 0) {
            #pragma unroll
            for (int nbo = 0; nbo < 8; ++nbo) {
                int col = nbo * 8 + (lane & 3) * 2;
                *(float2*)&Ored[rg * ORED_STRIDE + col]       = make_float2(o[nbo][0], o[nbo][1]);
                *(float2*)&Ored[(rg + 8) * ORED_STRIDE + col] = make_float2(o[nbo][2], o[nbo][3]);
            }
        }
        __syncthreads();
        if (wc == 1) {
            float inv0 = 1.0f / (l0 + red[rg]);
            float inv1 = 1.0f / (l1 + red[rg + 8]);
            float* op0 = out + ((size_t)(b * T_) + rowg0 + rg) * 64;
            float* op1 = op0 + 8 * 64;
            #pragma unroll
            for (int nbo = 0; nbo < 8; ++nbo) {
                int col = nbo * 8 + (lane & 3) * 2;
                float2 a0 = *(float2*)&Ored[rg * ORED_STRIDE + col];
                float2 a1 = *(float2*)&Ored[(rg + 8) * ORED_STRIDE + col];
                *(float2*)(op0 + col) = make_float2((a0.x + o[nbo][0]) * inv0,
                                                    (a0.y + o[nbo][1]) * inv0);
                *(float2*)(op1 + col) = make_float2((a1.x + o[nbo][2]) * inv1,
                                                    (a1.y + o[nbo][3]) * inv1);
            }
        }
        __syncthreads();        // red/Ored reuse by next phase
    }
}

// ---------------- launch ----------------
extern "C" void kernel_launch(void* const* d_in, const int* in_sizes, int n_in,
                              void* d_out, int out_size) {
    const float* x  = (const float*)d_in[0];
    const float* Wq = (const float*)d_in[1];
    const float* Wk = (const float*)d_in[2];
    const float* Wv = (const float*)d_in[3];
    const float* E  = (const float*)d_in[4];
    const float* F  = (const float*)d_in[5];
    float* out = (float*)d_out;

    combine_w_kernel<<<(192 * 1024) / 256, 256>>>(Wq, Wk, Wv, E, F);

    cudaFuncSetAttribute(proj_mma_kernel, cudaFuncAttributeMaxDynamicSharedMemorySize, PROJ_SMEM_BYTES);
    proj_mma_kernel<<<BT_ / 128, 256, PROJ_SMEM_BYTES>>>(x);

    cudaFuncSetAttribute(attn_mma_kernel, cudaFuncAttributeMaxDynamicSharedMemorySize, ATTN_SMEM_BYTES);
    attn_mma_kernel<<<dim3(16, B_), 256, ATTN_SMEM_BYTES>>>(out);
}

// round 10
// speedup vs baseline: 3.1804x; 1.0821x over previous
#include <cuda_runtime.h>
#include <cuda_bf16.h>
#include <cstdint>

#define B_  8
#define T_  2048
#define C_  1024
#define H_  64
#define BT_  (B_ * T_)          // 16384
#define BTH_ (BT_ * H_)         // 1048576

// ---------------- device scratch (no allocations allowed) ----------------
__device__ __nv_bfloat16 g_W3h[192 * 1024];
__device__ __nv_bfloat16 g_W3l[192 * 1024];
// hi/lo bf16 split of projected Q (pre-scaled), Kp, Vp — [B,T,H] row-major
__device__ __nv_bfloat16 g_qh[BTH_], g_ql[BTH_];
__device__ __nv_bfloat16 g_kh[BTH_], g_kl[BTH_];
__device__ __nv_bfloat16 g_vh[BTH_], g_vl[BTH_];

// ================= helpers =================
__device__ __forceinline__ uint32_t smem_u32(const void* p) {
    uint32_t a;
    asm("{ .reg .u64 t; cvta.to.shared.u64 t, %1; cvt.u32.u64 %0, t; }" : "=r"(a) : "l"(p));
    return a;
}
__device__ __forceinline__ float ex2f(float x) {
    float y;
    asm("ex2.approx.ftz.f32 %0, %1;" : "=f"(y) : "f"(x));
    return y;
}
__device__ __forceinline__ uint32_t pack_bf16(__nv_bfloat16 a, __nv_bfloat16 b) {
    __nv_bfloat162 t(a, b);
    return *reinterpret_cast<uint32_t*>(&t);
}
__device__ __forceinline__ void split2(float v0, float v1, uint32_t& h, uint32_t& l) {
    __nv_bfloat16 h0 = __float2bfloat16(v0), h1 = __float2bfloat16(v1);
    float r0 = v0 - __bfloat162float(h0), r1 = v1 - __bfloat162float(h1);
    h = pack_bf16(h0, h1);
    l = pack_bf16(__float2bfloat16(r0), __float2bfloat16(r1));
}
#define LDSM4(r, addr) \
    asm volatile("ldmatrix.sync.aligned.m8n8.x4.shared.b16 {%0,%1,%2,%3}, [%4];" \
                 : "=r"((r)[0]), "=r"((r)[1]), "=r"((r)[2]), "=r"((r)[3]) : "r"(addr))
#define LDSM4T(r, addr) \
    asm volatile("ldmatrix.sync.aligned.m8n8.x4.trans.shared.b16 {%0,%1,%2,%3}, [%4];" \
                 : "=r"((r)[0]), "=r"((r)[1]), "=r"((r)[2]), "=r"((r)[3]) : "r"(addr))
#define MMA16816(c, a, b0, b1) \
    asm volatile("mma.sync.aligned.m16n8k16.row.col.f32.bf16.bf16.f32 " \
                 "{%0,%1,%2,%3}, {%4,%5,%6,%7}, {%8,%9}, {%0,%1,%2,%3};" \
                 : "+f"((c)[0]), "+f"((c)[1]), "+f"((c)[2]), "+f"((c)[3]) \
                 : "r"((a)[0]), "r"((a)[1]), "r"((a)[2]), "r"((a)[3]), "r"(b0), "r"(b1))
#define CP_ASYNC16(dst, src) \
    asm volatile("cp.async.cg.shared.global [%0], [%1], 16;" :: "r"(dst), "l"(src))
#define CP_COMMIT() asm volatile("cp.async.commit_group;")
#define CP_WAIT(n)  asm volatile("cp.async.wait_group %0;" :: "n"(n))

// ---------------- kernel 1: fuse E/F into K/V weights (smem-staged column) ----------------
// Grid 192 (one output row n per block), 256 threads, 4 cols each.
__global__ void combine_w_kernel(const float* __restrict__ Wq, const float* __restrict__ Wk,
                                 const float* __restrict__ Wv, const float* __restrict__ E,
                                 const float* __restrict__ F) {
    __shared__ float col[64];
    const int n = blockIdx.x;
    const int tid = threadIdx.x;
    const int c4 = tid * 4;

    float4 v;
    if (n < 64) {
        v = *(const float4*)(Wq + (size_t)n * 1024 + c4);
    } else {
        const bool isK = (n < 128);
        const int d = isK ? (n - 64) : (n - 128);
        const float* M = isK ? E : F;
        const float* W = isK ? Wk : Wv;
        if (tid < 64) col[tid] = M[tid * 64 + d];
        __syncthreads();
        float4 s = make_float4(0.f, 0.f, 0.f, 0.f);
        #pragma unroll
        for (int h = 0; h < 64; ++h) {
            float e = col[h];
            float4 w = *(const float4*)(W + (size_t)h * 1024 + c4);
            s.x += e * w.x; s.y += e * w.y; s.z += e * w.z; s.w += e * w.w;
        }
        v = s;
    }
    uint32_t h01, l01, h23, l23;
    split2(v.x, v.y, h01, l01);
    split2(v.z, v.w, h23, l23);
    *(uint2*)&g_W3h[(size_t)n * 1024 + c4] = make_uint2(h01, h23);
    *(uint2*)&g_W3l[(size_t)n * 1024 + c4] = make_uint2(l01, l23);
}

// ---------------- kernel 2: merged mma.sync projection GEMM + x register pipeline ----------------
#define ASTRIDE 40
#define PROJ_A_ELEMS (128 * ASTRIDE)
#define PROJ_B_ELEMS (192 * ASTRIDE)
#define PROJ_SMEM_BYTES ((2 * PROJ_A_ELEMS + 2 * PROJ_B_ELEMS) * 2)   // 51200

__global__ __launch_bounds__(256, 1) void proj_mma_kernel(const float* __restrict__ x) {
    extern __shared__ __nv_bfloat16 psm[];
    __nv_bfloat16* Ah = psm;
    __nv_bfloat16* Al = Ah + PROJ_A_ELEMS;
    __nv_bfloat16* Bh = Al + PROJ_A_ELEMS;
    __nv_bfloat16* Bl = Bh + PROJ_B_ELEMS;

    const int tid = threadIdx.x;
    const int lane = tid & 31, w = tid >> 5;
    const int wm = w & 3, wn = w >> 2;
    const int m0 = blockIdx.x * 128;

    float c[3][2][4][4];
    #pragma unroll
    for (int n = 0; n < 3; ++n)
        #pragma unroll
        for (int i = 0; i < 2; ++i)
            #pragma unroll
            for (int j = 0; j < 4; ++j)
                #pragma unroll
                for (int q = 0; q < 4; ++q) c[n][i][j][q] = 0.f;

    const int arow = wm * 32 + (lane & 15);
    const int brow = wn * 32 + (lane & 15);
    const int koff = (lane >> 4) * 8;

    // register pipeline: preload x chunk 0
    const int xrow = tid >> 3, xc4 = (tid & 7) * 4;   // each thread: 4 rows spaced 32
    float4 xr[4];
    #pragma unroll
    for (int u = 0; u < 4; ++u)
        xr[u] = *(const float4*)(x + (size_t)(m0 + xrow + u * 32) * 1024 + xc4);

    for (int kt = 0; kt < 1024; kt += 32) {
        __syncthreads();
        // A tile: convert prefetched registers -> bf16 hi/lo smem
        #pragma unroll
        for (int u = 0; u < 4; ++u) {
            float4 v = xr[u];
            int row = xrow + u * 32;
            __nv_bfloat16 h0 = __float2bfloat16(v.x), h1 = __float2bfloat16(v.y);
            __nv_bfloat16 h2 = __float2bfloat16(v.z), h3 = __float2bfloat16(v.w);
            __nv_bfloat16 l0 = __float2bfloat16(v.x - __bfloat162float(h0));
            __nv_bfloat16 l1 = __float2bfloat16(v.y - __bfloat162float(h1));
            __nv_bfloat16 l2 = __float2bfloat16(v.z - __bfloat162float(h2));
            __nv_bfloat16 l3 = __float2bfloat16(v.w - __bfloat162float(h3));
            *(uint2*)&Ah[row * ASTRIDE + xc4] = make_uint2(pack_bf16(h0, h1), pack_bf16(h2, h3));
            *(uint2*)&Al[row * ASTRIDE + xc4] = make_uint2(pack_bf16(l0, l1), pack_bf16(l2, l3));
        }
        // B tile: 192 weight rows x 32, hi/lo (L2-hot)
        #pragma unroll
        for (int u = 0; u < 3; ++u) {
            int idx = tid + u * 256;
            int row = idx >> 2, c8 = (idx & 3) * 8;
            size_t g = (size_t)row * 1024 + kt + c8;
            *(uint4*)&Bh[row * ASTRIDE + c8] = *(const uint4*)(g_W3h + g);
            *(uint4*)&Bl[row * ASTRIDE + c8] = *(const uint4*)(g_W3l + g);
        }
        __syncthreads();

        // issue next chunk's x loads early — latency hides under the mma section
        if (kt + 32 < 1024) {
            #pragma unroll
            for (int u = 0; u < 4; ++u)
                xr[u] = *(const float4*)(x + (size_t)(m0 + xrow + u * 32) * 1024 + (kt + 32) + xc4);
        }

        #pragma unroll
        for (int p = 0; p < 3; ++p) {
            const __nv_bfloat16* As = (p == 1) ? Al : Ah;
            const __nv_bfloat16* Bs = (p == 2) ? Bl : Bh;
            #pragma unroll
            for (int k16 = 0; k16 < 2; ++k16) {
                uint32_t a[2][4];
                #pragma unroll
                for (int s = 0; s < 2; ++s)
                    LDSM4(a[s], smem_u32(&As[(arow + s * 16) * ASTRIDE + k16 * 16 + koff]));
                #pragma unroll
                for (int nblk = 0; nblk < 3; ++nblk) {
                    uint32_t b[2][4];
                    #pragma unroll
                    for (int s = 0; s < 2; ++s)
                        LDSM4(b[s], smem_u32(&Bs[(nblk * 64 + brow + s * 16) * ASTRIDE + k16 * 16 + koff]));
                    #pragma unroll
                    for (int ms = 0; ms < 2; ++ms)
                        #pragma unroll
                        for (int nb = 0; nb < 4; ++nb)
                            MMA16816(c[nblk][ms][nb], a[ms], b[nb >> 1][nb & 1], b[nb >> 1][(nb & 1) + 2]);
                }
            }
        }
    }

    #pragma unroll
    for (int nblk = 0; nblk < 3; ++nblk) {
        const float scale = (nblk == 0) ? (0.0625f * 1.4426950408889634f) : 1.0f;
        __nv_bfloat16* ph = (nblk == 0) ? g_qh : (nblk == 1 ? g_kh : g_vh);
        __nv_bfloat16* pl = (nblk == 0) ? g_ql : (nblk == 1 ? g_kl : g_vl);
        #pragma unroll
        for (int ms = 0; ms < 2; ++ms) {
            int r0 = m0 + wm * 32 + ms * 16 + (lane >> 2);
            #pragma unroll
            for (int nb = 0; nb < 4; ++nb) {
                int col = wn * 32 + nb * 8 + (lane & 3) * 2;
                uint32_t h, l;
                split2(c[nblk][ms][nb][0] * scale, c[nblk][ms][nb][1] * scale, h, l);
                *(uint32_t*)&ph[(size_t)r0 * 64 + col] = h;
                *(uint32_t*)&pl[(size_t)r0 * 64 + col] = l;
                split2(c[nblk][ms][nb][2] * scale, c[nblk][ms][nb][3] * scale, h, l);
                *(uint32_t*)&ph[(size_t)(r0 + 8) * 64 + col] = h;
                *(uint32_t*)&pl[(size_t)(r0 + 8) * 64 + col] = l;
            }
        }
    }
}

// ---------------- kernel 3: balanced attention, independent per-half softmax ----------------
// CTA = q-tile pair (p, 31-p), 17 key-iters, 8 warps = 4 row-groups x 2 key halves.
// Each half runs a PRIVATE online softmax (no mid-iter exchange/sync); halves are
// merged once per phase in the epilogue: O = O_a*2^(m_a-M) + O_b*2^(m_b-M).
#define QSTRIDE 72
#define TEN_ELEMS (128 * QSTRIDE)
#define STAGE_ELEMS (4 * TEN_ELEMS)
#define BF16_ELEMS (2 * TEN_ELEMS + 2 * STAGE_ELEMS)
#define ORED_STRIDE 66
#define ATTN_SMEM_BYTES (BF16_ELEMS * 2 + 64 * ORED_STRIDE * 4 + 3 * 64 * 4)   // 202,752

__global__ __launch_bounds__(256, 1) void attn_mma_kernel(float* __restrict__ out) {
    extern __shared__ __nv_bfloat16 sb[];
    __nv_bfloat16* Qh = sb;
    __nv_bfloat16* Ql = sb + TEN_ELEMS;
    __nv_bfloat16* Stg = sb + 2 * TEN_ELEMS;          // [2][4][TEN_ELEMS]
    float* Ored = (float*)(sb + BF16_ELEMS);          // [64][ORED_STRIDE]
    float* redm = Ored + 64 * ORED_STRIDE;            // [2][64] running max per half
    float* redl = redm + 2 * 64;                      // [64]    wc=0's scaled l

    const int b = blockIdx.y;
    const int p = blockIdx.x;
    const int tid = threadIdx.x;
    const int lane = tid & 31, w = tid >> 5;
    const int wr = w & 3;
    const int wc = w >> 2;
    const size_t kvbase = (size_t)(b * T_) * H_;
    const int qts[2] = {p, 31 - p};

    #pragma unroll
    for (int u = 0; u < 4; ++u) {
        int idx = tid + u * 256;
        int row = idx >> 3, c8 = (idx & 7) * 8;
        size_t g = ((size_t)(b * T_) + qts[row >> 6] * 64 + (row & 63)) * H_ + c8;
        *(uint4*)&Qh[row * QSTRIDE + c8] = *(const uint4*)(g_qh + g);
        *(uint4*)&Ql[row * QSTRIDE + c8] = *(const uint4*)(g_ql + g);
    }

    const __nv_bfloat16* gsrc[4] = {g_kh, g_kl, g_vh, g_vl};
    auto prefetch = [&](int stg, int kt) {
        __nv_bfloat16* dst = Stg + stg * STAGE_ELEMS;
        size_t base = kvbase + (size_t)kt * 128 * 64;
        #pragma unroll
        for (int t = 0; t < 4; ++t) {
            #pragma unroll
            for (int u = 0; u < 4; ++u) {
                int idx = tid + u * 256;
                int row = idx >> 3, c8 = (idx & 7) * 8;
                CP_ASYNC16(smem_u32(&dst[t * TEN_ELEMS + row * QSTRIDE + c8]),
                           gsrc[t] + base + (size_t)row * 64 + c8);
            }
        }
    };

    prefetch(0, 0);
    CP_COMMIT();

    int sidx = 0;
    const int koff = (lane >> 4) * 8;
    const int r0loc = lane >> 2;
    const int rg = wr * 16 + r0loc;

    #pragma unroll 1
    for (int phase = 0; phase < 2; ++phase) {
        const int qt = qts[phase];
        const int rowg0 = qt * 64;
        const int ntiles = (qt >> 1) + 1;
        const int arow = phase * 64 + wr * 16 + (lane & 15);

        float m0 = -1e30f, m1 = -1e30f, l0 = 0.f, l1 = 0.f;
        float o[8][4];
        #pragma unroll
        for (int i = 0; i < 8; ++i)
            #pragma unroll
            for (int q = 0; q < 4; ++q) o[i][q] = 0.f;

        for (int kt = 0; kt < ntiles; ++kt) {
            if (kt + 1 < ntiles) {
                prefetch(sidx ^ 1, kt + 1);  CP_COMMIT();  CP_WAIT(1);
            } else if (phase == 0) {
                prefetch(sidx ^ 1, 0);       CP_COMMIT();  CP_WAIT(1);
            } else {
                CP_WAIT(0);
            }
            __syncthreads();

            const __nv_bfloat16* Kh = Stg + sidx * STAGE_ELEMS;
            const __nv_bfloat16* Kl = Kh + TEN_ELEMS;
            const __nv_bfloat16* Vh = Kh + 2 * TEN_ELEMS;
            const __nv_bfloat16* Vl = Kh + 3 * TEN_ELEMS;

            // ---- S = Q @ K^T over this warp's 64-key half (hh + lh + hl) ----
            float s[8][4];
            #pragma unroll
            for (int nb = 0; nb < 8; ++nb)
                #pragma unroll
                for (int q = 0; q < 4; ++q) s[nb][q] = 0.f;

            #pragma unroll
            for (int k16 = 0; k16 < 4; ++k16) {
                uint32_t ah[4], al[4];
                LDSM4(ah, smem_u32(&Qh[arow * QSTRIDE + k16 * 16 + koff]));
                LDSM4(al, smem_u32(&Ql[arow * QSTRIDE + k16 * 16 + koff]));
                #pragma unroll
                for (int g = 0; g < 4; ++g) {
                    uint32_t bh[4], bl[4];
                    int krow = wc * 64 + g * 16 + (lane & 15);
                    LDSM4(bh, smem_u32(&Kh[krow * QSTRIDE + k16 * 16 + koff]));
                    LDSM4(bl, smem_u32(&Kl[krow * QSTRIDE + k16 * 16 + koff]));
                    MMA16816(s[2 * g],     ah, bh[0], bh[2]);
                    MMA16816(s[2 * g],     al, bh[0], bh[2]);
                    MMA16816(s[2 * g],     ah, bl[0], bl[2]);
                    MMA16816(s[2 * g + 1], ah, bh[1], bh[3]);
                    MMA16816(s[2 * g + 1], al, bh[1], bh[3]);
                    MMA16816(s[2 * g + 1], ah, bl[1], bl[3]);
                }
            }

            // ---- causal mask (diagonal iter only) ----
            if (kt == ntiles - 1) {
                int ig0 = rowg0 + rg;
                #pragma unroll
                for (int nb = 0; nb < 8; ++nb) {
                    int cg = kt * 128 + wc * 64 + nb * 8 + (lane & 3) * 2;
                    if (cg > ig0)         s[nb][0] = -1e30f;
                    if (cg + 1 > ig0)     s[nb][1] = -1e30f;
                    if (cg > ig0 + 8)     s[nb][2] = -1e30f;
                    if (cg + 1 > ig0 + 8) s[nb][3] = -1e30f;
                }
            }

            // ---- private online softmax for this key half (no cross-half sync) ----
            float mx0 = -1e30f, mx1 = -1e30f;
            #pragma unroll
            for (int nb = 0; nb < 8; ++nb) {
                mx0 = fmaxf(mx0, fmaxf(s[nb][0], s[nb][1]));
                mx1 = fmaxf(mx1, fmaxf(s[nb][2], s[nb][3]));
            }
            mx0 = fmaxf(mx0, __shfl_xor_sync(0xffffffffu, mx0, 1));
            mx0 = fmaxf(mx0, __shfl_xor_sync(0xffffffffu, mx0, 2));
            mx1 = fmaxf(mx1, __shfl_xor_sync(0xffffffffu, mx1, 1));
            mx1 = fmaxf(mx1, __shfl_xor_sync(0xffffffffu, mx1, 2));

            float mn0 = fmaxf(m0, mx0), mn1 = fmaxf(m1, mx1);
            float al0 = ex2f(m0 - mn0), al1 = ex2f(m1 - mn1);
            m0 = mn0; m1 = mn1;
            #pragma unroll
            for (int i = 0; i < 8; ++i) {
                o[i][0] *= al0; o[i][1] *= al0;
                o[i][2] *= al1; o[i][3] *= al1;
            }
            float rs0 = 0.f, rs1 = 0.f;
            #pragma unroll
            for (int nb = 0; nb < 8; ++nb) {
                float p0 = ex2f(s[nb][0] - mn0); s[nb][0] = p0; rs0 += p0;
                float p1 = ex2f(s[nb][1] - mn0); s[nb][1] = p1; rs0 += p1;
                float p2 = ex2f(s[nb][2] - mn1); s[nb][2] = p2; rs1 += p2;
                float p3 = ex2f(s[nb][3] - mn1); s[nb][3] = p3; rs1 += p3;
            }
            rs0 += __shfl_xor_sync(0xffffffffu, rs0, 1);
            rs0 += __shfl_xor_sync(0xffffffffu, rs0, 2);
            rs1 += __shfl_xor_sync(0xffffffffu, rs1, 1);
            rs1 += __shfl_xor_sync(0xffffffffu, rs1, 2);
            l0 = l0 * al0 + rs0;
            l1 = l1 * al1 + rs1;

            // ---- O += P @ V over this warp's 64-key half ----
            #pragma unroll
            for (int kb = 0; kb < 4; ++kb) {
                uint32_t ph[4], pl[4];
                split2(s[2 * kb][0],     s[2 * kb][1],     ph[0], pl[0]);
                split2(s[2 * kb][2],     s[2 * kb][3],     ph[1], pl[1]);
                split2(s[2 * kb + 1][0], s[2 * kb + 1][1], ph[2], pl[2]);
                split2(s[2 * kb + 1][2], s[2 * kb + 1][3], ph[3], pl[3]);
                #pragma unroll
                for (int g = 0; g < 4; ++g) {
                    uint32_t bh[4], bl[4];
                    int vrow = wc * 64 + kb * 16 + (lane & 15);
                    LDSM4T(bh, smem_u32(&Vh[vrow * QSTRIDE + g * 16 + koff]));
                    LDSM4T(bl, smem_u32(&Vl[vrow * QSTRIDE + g * 16 + koff]));
                    MMA16816(o[2 * g],     ph, bh[0], bh[1]);
                    MMA16816(o[2 * g],     pl, bh[0], bh[1]);
                    MMA16816(o[2 * g],     ph, bl[0], bl[1]);
                    MMA16816(o[2 * g + 1], ph, bh[2], bh[3]);
                    MMA16816(o[2 * g + 1], pl, bh[2], bh[3]);
                    MMA16816(o[2 * g + 1], ph, bl[2], bl[3]);
                }
            }
            sidx ^= 1;
            __syncthreads();    // stage consumed before overwrite
        }

        // ---- phase epilogue: merge the two key halves ----
        if ((lane & 3) == 0) {
            redm[wc * 64 + rg]     = m0;
            redm[wc * 64 + rg + 8] = m1;
        }
        __syncthreads();
        {
            float mo0 = redm[(wc ^ 1) * 64 + rg];
            float mo1 = redm[(wc ^ 1) * 64 + rg + 8];
            float M0 = fmaxf(m0, mo0), M1 = fmaxf(m1, mo1);
            float sc0 = ex2f(m0 - M0), sc1 = ex2f(m1 - M1);
            l0 *= sc0; l1 *= sc1;
            #pragma unroll
            for (int i = 0; i < 8; ++i) {
                o[i][0] *= sc0; o[i][1] *= sc0;
                o[i][2] *= sc1; o[i][3] *= sc1;
            }
        }
        if (wc == 0) {
            if ((lane & 3) == 0) { redl[rg] = l0; redl[rg + 8] = l1; }
            #pragma unroll
            for (int nbo = 0; nbo < 8; ++nbo) {
                int col = nbo * 8 + (lane & 3) * 2;
                *(float2*)&Ored[rg * ORED_STRIDE + col]       = make_float2(o[nbo][0], o[nbo][1]);
                *(float2*)&Ored[(rg + 8) * ORED_STRIDE + col] = make_float2(o[nbo][2], o[nbo][3]);
            }
        }
        __syncthreads();
        if (wc == 1) {
            float inv0 = 1.0f / (l0 + redl[rg]);
            float inv1 = 1.0f / (l1 + redl[rg + 8]);
            float* op0 = out + ((size_t)(b * T_) + rowg0 + rg) * 64;
            float* op1 = op0 + 8 * 64;
            #pragma unroll
            for (int nbo = 0; nbo < 8; ++nbo) {
                int col = nbo * 8 + (lane & 3) * 2;
                float2 a0 = *(float2*)&Ored[rg * ORED_STRIDE + col];
                float2 a1 = *(float2*)&Ored[(rg + 8) * ORED_STRIDE + col];
                *(float2*)(op0 + col) = make_float2((a0.x + o[nbo][0]) * inv0,
                                                    (a0.y + o[nbo][1]) * inv0);
                *(float2*)(op1 + col) = make_float2((a1.x + o[nbo][2]) * inv1,
                                                    (a1.y + o[nbo][3]) * inv1);
            }
        }
        __syncthreads();        // redm/redl/Ored reuse by next phase
    }
}

// ---------------- launch ----------------
extern "C" void kernel_launch(void* const* d_in, const int* in_sizes, int n_in,
                              void* d_out, int out_size) {
    const float* x  = (const float*)d_in[0];
    const float* Wq = (const float*)d_in[1];
    const float* Wk = (const float*)d_in[2];
    const float* Wv = (const float*)d_in[3];
    const float* E  = (const float*)d_in[4];
    const float* F  = (const float*)d_in[5];
    float* out = (float*)d_out;

    combine_w_kernel<<<192, 256>>>(Wq, Wk, Wv, E, F);

    cudaFuncSetAttribute(proj_mma_kernel, cudaFuncAttributeMaxDynamicSharedMemorySize, PROJ_SMEM_BYTES);
    proj_mma_kernel<<<BT_ / 128, 256, PROJ_SMEM_BYTES>>>(x);

    cudaFuncSetAttribute(attn_mma_kernel, cudaFuncAttributeMaxDynamicSharedMemorySize, ATTN_SMEM_BYTES);
    attn_mma_kernel<<<dim3(16, B_), 256, ATTN_SMEM_BYTES>>>(out);
}